// round 9
// baseline (speedup 1.0000x reference)
#include <cuda_runtime.h>
#include <cuda_bf16.h>
#include <math.h>
#include <stdint.h>

#define NN 50000
#define EE 800000
#define EMB 64
#define HID 128

// ---------------- scratch (device globals; no allocation allowed) ----------------
__device__ float g_deg[NN];
__device__ float g_dinv[NN];
__device__ int   g_cnt[NN];
__device__ int   g_off[NN + 1];
__device__ int   g_cur[NN];
__device__ int   g_srcs[EE];
__device__ float g_wsrt[EE];

// feature tensors as bf16 hi/lo planes
__device__ __align__(16) __nv_bfloat16 g_zhi[NN * EMB],  g_zlo[NN * EMB];
__device__ __align__(16) __nv_bfloat16 g_hhi[NN * HID],  g_hlo[NN * HID];
__device__ __align__(16) __nv_bfloat16 g_p1hi[NN * HID], g_p1lo[NN * HID];
__device__ __align__(16) __nv_bfloat16 g_p2hi[NN * HID], g_p2lo[NN * HID];
__device__ __align__(16) __nv_bfloat16 g_p3hi[NN * HID], g_p3lo[NN * HID];
__device__ __align__(16) __nv_bfloat16 g_y0hi[NN * EMB], g_y0lo[NN * EMB];
__device__ __align__(16) __nv_bfloat16 g_y1hi[NN * EMB], g_y1lo[NN * EMB];
__device__ __align__(16) __nv_bfloat16 g_y2hi[NN * EMB], g_y2lo[NN * EMB];
__device__ __align__(16) __nv_bfloat16 g_y3hi[NN * EMB], g_y3lo[NN * EMB];

__device__ __align__(16) float g_pp1[NN * 3];
__device__ __align__(16) float g_pp2[NN * 3];
__device__ __align__(16) float g_pp3[NN * 3];
__device__ __align__(16) float g_posacc[NN * HID];

// pre-split, pre-transposed weights: [hop][s=hi/lo][n(128)][k(CINH)] bf16
__device__ __align__(16) __nv_bfloat16 g_wt1[4 * 2 * 128 * 64];
__device__ __align__(16) __nv_bfloat16 g_wt2[4 * 2 * 128 * 128];
__device__ __align__(16) __nv_bfloat16 g_wt3[2 * 2 * 128 * 128];

__device__ __forceinline__ float gelu_exact(float x) {
    return 0.5f * x * (1.0f + erff(x * 0.70710678118654752f));
}

// reconstruct 2 fp32 from packed hi/lo bf16x2
__device__ __forceinline__ float2 rec2(uint32_t h, uint32_t l) {
    float2 a = __bfloat1622float2(*reinterpret_cast<__nv_bfloat162*>(&h));
    float2 b = __bfloat1622float2(*reinterpret_cast<__nv_bfloat162*>(&l));
    return make_float2(a.x + b.x, a.y + b.y);
}
// split 2 fp32 into packed hi/lo bf16x2
__device__ __forceinline__ void split2(float x, float y, uint32_t& hi, uint32_t& lo) {
    __nv_bfloat16 hx = __float2bfloat16(x), hy = __float2bfloat16(y);
    __nv_bfloat16 lx = __float2bfloat16(x - __bfloat162float(hx));
    __nv_bfloat16 ly = __float2bfloat16(y - __bfloat162float(hy));
    hi = (uint32_t)__bfloat16_as_ushort(hx) | ((uint32_t)__bfloat16_as_ushort(hy) << 16);
    lo = (uint32_t)__bfloat16_as_ushort(lx) | ((uint32_t)__bfloat16_as_ushort(ly) << 16);
}

// ---------------- mma.sync helper (bf16, m16n8k16, fp32 acc) ----------------
__device__ __forceinline__ void mma16816(float* d, const uint32_t* a, uint32_t b0, uint32_t b1) {
    asm volatile(
        "mma.sync.aligned.m16n8k16.row.col.f32.bf16.bf16.f32 "
        "{%0,%1,%2,%3}, {%4,%5,%6,%7}, {%8,%9}, {%0,%1,%2,%3};"
        : "+f"(d[0]), "+f"(d[1]), "+f"(d[2]), "+f"(d[3])
        : "r"(a[0]), "r"(a[1]), "r"(a[2]), "r"(a[3]), "r"(b0), "r"(b1));
}

// ---------------- setup kernels ----------------
__global__ void k_zero() {
    int i = blockIdx.x * blockDim.x + threadIdx.x;
    if (i < NN) { g_deg[i] = 0.f; g_cnt[i] = 0; }
}

__global__ void k_hist(const int* __restrict__ col, const float* __restrict__ ea) {
    int e = blockIdx.x * blockDim.x + threadIdx.x;
    if (e < EE) {
        int c = col[e];
        atomicAdd(&g_deg[c], ea[e]);
        atomicAdd(&g_cnt[c], 1);
    }
}

__global__ void k_dinv() {
    int i = blockIdx.x * blockDim.x + threadIdx.x;
    if (i < NN) {
        float d = g_deg[i];
        g_dinv[i] = (d > 0.f) ? rsqrtf(d) : 0.f;
    }
}

__global__ void k_scan() {
    __shared__ int sh[1024];
    int tid = threadIdx.x;
    int carry = 0;
    for (int base = 0; base < NN; base += 1024) {
        int i = base + tid;
        int v = (i < NN) ? g_cnt[i] : 0;
        sh[tid] = v;
        __syncthreads();
        for (int ofs = 1; ofs < 1024; ofs <<= 1) {
            int t = (tid >= ofs) ? sh[tid - ofs] : 0;
            __syncthreads();
            sh[tid] += t;
            __syncthreads();
        }
        if (i < NN) g_off[i] = carry + sh[tid] - v;
        carry += sh[1023];
        __syncthreads();
    }
    if (tid == 0) g_off[NN] = carry;
}

__global__ void k_cursor() {
    int i = blockIdx.x * blockDim.x + threadIdx.x;
    if (i < NN) g_cur[i] = g_off[i];
}

__global__ void k_scatter(const int* __restrict__ row, const int* __restrict__ col,
                          const float* __restrict__ ea) {
    int e = blockIdx.x * blockDim.x + threadIdx.x;
    if (e < EE) {
        int r = row[e], c = col[e];
        int p = atomicAdd(&g_cur[c], 1);
        g_srcs[p] = r;
        g_wsrt[p] = g_dinv[r] * ea[e] * g_dinv[c];
    }
}

// ---------------- weight prep: transpose + bf16 hi/lo split ----------------
__device__ __forceinline__ void split_store(__nv_bfloat16* hi, __nv_bfloat16* lo, float w) {
    __nv_bfloat16 hb = __float2bfloat16(w);
    *hi = hb;
    *lo = __float2bfloat16(w - __bfloat162float(hb));
}

__global__ void k_wprep1(const float* __restrict__ c1w) {   // [4][67][128] -> g_wt1 [4][2][128][64]
    int idx = blockIdx.x * blockDim.x + threadIdx.x;
    if (idx >= 4 * 128 * 64) return;
    int hop = idx / (128 * 64);
    int r = idx - hop * 128 * 64;
    int n = r >> 6, k = r & 63;
    float w = c1w[hop * 67 * 128 + k * 128 + n];
    size_t b = ((size_t)(hop * 2) * 128 + n) * 64 + k;
    split_store(&g_wt1[b], &g_wt1[b + 128 * 64], w);
}

__global__ void k_wprep2(const float* __restrict__ c2w) {   // [4][128][128] -> g_wt2 [4][2][128][128]
    int idx = blockIdx.x * blockDim.x + threadIdx.x;
    if (idx >= 4 * 128 * 128) return;
    int hop = idx / (128 * 128);
    int r = idx - hop * 128 * 128;
    int n = r >> 7, k = r & 127;
    float w = c2w[hop * 128 * 128 + k * 128 + n];
    size_t b = ((size_t)(hop * 2) * 128 + n) * 128 + k;
    split_store(&g_wt2[b], &g_wt2[b + 128 * 128], w);
}

__global__ void k_wprep3(const float* __restrict__ c3w) {   // [4][128][64] -> g_wt3 [2 pairs][2][128][128]
    int idx = blockIdx.x * blockDim.x + threadIdx.x;
    if (idx >= 2 * 128 * 128) return;
    int pair = idx / (128 * 128);
    int r = idx - pair * 128 * 128;
    int n = r >> 7, k = r & 127;
    int wk = pair * 2 + (n >> 6);
    int nn = n & 63;
    float w = c3w[wk * 128 * 64 + k * 64 + nn];
    size_t b = ((size_t)(pair * 2) * 128 + n) * 128 + k;
    split_store(&g_wt3[b], &g_wt3[b + 128 * 128], w);
}

// ---------------- pos hops + posacc ----------------
__global__ void k_prop3(float* __restrict__ dst, const float* __restrict__ src) {
    int j = blockIdx.x * blockDim.x + threadIdx.x;
    if (j >= NN) return;
    int beg = g_off[j], end = g_off[j + 1];
    float a0 = 0.f, a1 = 0.f, a2 = 0.f;
    for (int e = beg; e < end; e++) {
        int s = g_srcs[e];
        float w = g_wsrt[e];
        a0 += w * src[s * 3 + 0];
        a1 += w * src[s * 3 + 1];
        a2 += w * src[s * 3 + 2];
    }
    dst[j * 3 + 0] = a0; dst[j * 3 + 1] = a1; dst[j * 3 + 2] = a2;
}

__global__ void k_posacc(const float* __restrict__ pos, const float* __restrict__ c1w) {
    int idx = blockIdx.x * blockDim.x + threadIdx.x;
    if (idx >= NN * HID) return;
    int n = idx >> 7, c = idx & 127;
    const float* pps[4] = {pos, g_pp1, g_pp2, g_pp3};
    float acc = 0.f;
#pragma unroll
    for (int k = 0; k < 4; k++) {
        const float* pp = pps[k] + n * 3;
        const float* wr = c1w + k * 67 * 128 + 64 * 128 + c;
        acc += pp[0] * wr[0] + pp[1] * wr[128] + pp[2] * wr[256];
    }
    g_posacc[idx] = acc;
}

// ---------------- up MLP: z0 planes ----------------
__global__ __launch_bounds__(256) void k_up(const float* __restrict__ x,
                                            const float* __restrict__ w1, const float* __restrict__ b1,
                                            const float* __restrict__ w2, const float* __restrict__ b2) {
    __shared__ float sw2[64 * 64];
    __shared__ float hid[4][64];
    int tid = threadIdx.x;
#pragma unroll
    for (int i = 0; i < 16; i++) sw2[tid * 16 + i] = w2[tid * 16 + i];
    int local = tid >> 6;
    int c = tid & 63;
    int node = blockIdx.x * 4 + local;
    float h = 0.f;
    if (node < NN) {
        h = b1[c];
#pragma unroll
        for (int i = 0; i < 4; i++) h += x[node * 4 + i] * w1[i * 64 + c];
        h = gelu_exact(h);
    }
    hid[local][c] = h;
    __syncthreads();
    if (node < NN) {
        float o = b2[c];
#pragma unroll
        for (int j = 0; j < 64; j++) o += hid[local][j] * sw2[j * 64 + c];
        __nv_bfloat16 hb = __float2bfloat16(o);
        g_zhi[node * 64 + c] = hb;
        g_zlo[node * 64 + c] = __float2bfloat16(o - __bfloat162float(hb));
    }
}

// ---------------- propagation kernels (CSR, warp per node, hi/lo planes) -----------
__global__ __launch_bounds__(256) void k_prop64(__nv_bfloat16* __restrict__ dhi, __nv_bfloat16* __restrict__ dlo,
                                                const __nv_bfloat16* __restrict__ shi,
                                                const __nv_bfloat16* __restrict__ slo) {
    int wrp = threadIdx.x >> 5, lane = threadIdx.x & 31;
    int j = blockIdx.x * 8 + wrp;
    if (j >= NN) return;
    int beg = g_off[j], end = g_off[j + 1];
    float2 a0 = {0.f, 0.f}, a1 = {0.f, 0.f};
    int e = beg;
    for (; e + 2 <= end; e += 2) {
        int s0 = g_srcs[e], s1 = g_srcs[e + 1];
        float w0 = g_wsrt[e], w1 = g_wsrt[e + 1];
        uint32_t h0 = *(const uint32_t*)(shi + (size_t)s0 * 64 + lane * 2);
        uint32_t l0 = *(const uint32_t*)(slo + (size_t)s0 * 64 + lane * 2);
        uint32_t h1 = *(const uint32_t*)(shi + (size_t)s1 * 64 + lane * 2);
        uint32_t l1 = *(const uint32_t*)(slo + (size_t)s1 * 64 + lane * 2);
        float2 v0 = rec2(h0, l0), v1 = rec2(h1, l1);
        a0.x = fmaf(w0, v0.x, a0.x); a0.y = fmaf(w0, v0.y, a0.y);
        a1.x = fmaf(w1, v1.x, a1.x); a1.y = fmaf(w1, v1.y, a1.y);
    }
    if (e < end) {
        int s0 = g_srcs[e];
        float w0 = g_wsrt[e];
        uint32_t h0 = *(const uint32_t*)(shi + (size_t)s0 * 64 + lane * 2);
        uint32_t l0 = *(const uint32_t*)(slo + (size_t)s0 * 64 + lane * 2);
        float2 v0 = rec2(h0, l0);
        a0.x = fmaf(w0, v0.x, a0.x); a0.y = fmaf(w0, v0.y, a0.y);
    }
    uint32_t hi, lo;
    split2(a0.x + a1.x, a0.y + a1.y, hi, lo);
    *(uint32_t*)(dhi + (size_t)j * 64 + lane * 2) = hi;
    *(uint32_t*)(dlo + (size_t)j * 64 + lane * 2) = lo;
}

__global__ __launch_bounds__(256) void k_prop128(__nv_bfloat16* __restrict__ dhi, __nv_bfloat16* __restrict__ dlo,
                                                 const __nv_bfloat16* __restrict__ shi,
                                                 const __nv_bfloat16* __restrict__ slo) {
    int wrp = threadIdx.x >> 5, lane = threadIdx.x & 31;
    int j = blockIdx.x * 8 + wrp;
    if (j >= NN) return;
    int beg = g_off[j], end = g_off[j + 1];
    float4 a0 = {0.f,0.f,0.f,0.f}, a1 = {0.f,0.f,0.f,0.f};
    int e = beg;
    for (; e + 2 <= end; e += 2) {
        int s0 = g_srcs[e], s1 = g_srcs[e + 1];
        float w0 = g_wsrt[e], w1 = g_wsrt[e + 1];
        uint2 h0 = *(const uint2*)(shi + (size_t)s0 * 128 + lane * 4);
        uint2 l0 = *(const uint2*)(slo + (size_t)s0 * 128 + lane * 4);
        uint2 h1 = *(const uint2*)(shi + (size_t)s1 * 128 + lane * 4);
        uint2 l1 = *(const uint2*)(slo + (size_t)s1 * 128 + lane * 4);
        float2 va = rec2(h0.x, l0.x), vb = rec2(h0.y, l0.y);
        a0.x = fmaf(w0, va.x, a0.x); a0.y = fmaf(w0, va.y, a0.y);
        a0.z = fmaf(w0, vb.x, a0.z); a0.w = fmaf(w0, vb.y, a0.w);
        float2 vc = rec2(h1.x, l1.x), vd = rec2(h1.y, l1.y);
        a1.x = fmaf(w1, vc.x, a1.x); a1.y = fmaf(w1, vc.y, a1.y);
        a1.z = fmaf(w1, vd.x, a1.z); a1.w = fmaf(w1, vd.y, a1.w);
    }
    if (e < end) {
        int s0 = g_srcs[e];
        float w0 = g_wsrt[e];
        uint2 h0 = *(const uint2*)(shi + (size_t)s0 * 128 + lane * 4);
        uint2 l0 = *(const uint2*)(slo + (size_t)s0 * 128 + lane * 4);
        float2 va = rec2(h0.x, l0.x), vb = rec2(h0.y, l0.y);
        a0.x = fmaf(w0, va.x, a0.x); a0.y = fmaf(w0, va.y, a0.y);
        a0.z = fmaf(w0, vb.x, a0.z); a0.w = fmaf(w0, vb.y, a0.w);
    }
    uint2 hi, lo;
    split2(a0.x + a1.x, a0.y + a1.y, hi.x, lo.x);
    split2(a0.z + a1.z, a0.w + a1.w, hi.y, lo.y);
    *(uint2*)(dhi + (size_t)j * 128 + lane * 4) = hi;
    *(uint2*)(dlo + (size_t)j * 128 + lane * 4) = lo;
}

// tag3: dst = P src + add   (64 channels, planes)
__global__ __launch_bounds__(256) void k_propadd64(__nv_bfloat16* __restrict__ dhi, __nv_bfloat16* __restrict__ dlo,
                                                   const __nv_bfloat16* __restrict__ shi,
                                                   const __nv_bfloat16* __restrict__ slo,
                                                   const __nv_bfloat16* __restrict__ ahi,
                                                   const __nv_bfloat16* __restrict__ alo) {
    int wrp = threadIdx.x >> 5, lane = threadIdx.x & 31;
    int j = blockIdx.x * 8 + wrp;
    if (j >= NN) return;
    int beg = g_off[j], end = g_off[j + 1];
    float2 a0 = {0.f, 0.f}, a1 = {0.f, 0.f};
    int e = beg;
    for (; e + 2 <= end; e += 2) {
        int s0 = g_srcs[e], s1 = g_srcs[e + 1];
        float w0 = g_wsrt[e], w1 = g_wsrt[e + 1];
        uint32_t h0 = *(const uint32_t*)(shi + (size_t)s0 * 64 + lane * 2);
        uint32_t l0 = *(const uint32_t*)(slo + (size_t)s0 * 64 + lane * 2);
        uint32_t h1 = *(const uint32_t*)(shi + (size_t)s1 * 64 + lane * 2);
        uint32_t l1 = *(const uint32_t*)(slo + (size_t)s1 * 64 + lane * 2);
        float2 v0 = rec2(h0, l0), v1 = rec2(h1, l1);
        a0.x = fmaf(w0, v0.x, a0.x); a0.y = fmaf(w0, v0.y, a0.y);
        a1.x = fmaf(w1, v1.x, a1.x); a1.y = fmaf(w1, v1.y, a1.y);
    }
    if (e < end) {
        int s0 = g_srcs[e];
        float w0 = g_wsrt[e];
        uint32_t h0 = *(const uint32_t*)(shi + (size_t)s0 * 64 + lane * 2);
        uint32_t l0 = *(const uint32_t*)(slo + (size_t)s0 * 64 + lane * 2);
        float2 v0 = rec2(h0, l0);
        a0.x = fmaf(w0, v0.x, a0.x); a0.y = fmaf(w0, v0.y, a0.y);
    }
    uint32_t xh = *(const uint32_t*)(ahi + (size_t)j * 64 + lane * 2);
    uint32_t xl = *(const uint32_t*)(alo + (size_t)j * 64 + lane * 2);
    float2 ad = rec2(xh, xl);
    uint32_t hi, lo;
    split2(a0.x + a1.x + ad.x, a0.y + a1.y + ad.y, hi, lo);
    *(uint32_t*)(dhi + (size_t)j * 64 + lane * 2) = hi;
    *(uint32_t*)(dlo + (size_t)j * 64 + lane * 2) = lo;
}

// tag3 final: z = log_softmax(P src + add + bias) -> z planes
__global__ __launch_bounds__(256) void k_proplogsm(const __nv_bfloat16* __restrict__ shi,
                                                   const __nv_bfloat16* __restrict__ slo,
                                                   const __nv_bfloat16* __restrict__ ahi,
                                                   const __nv_bfloat16* __restrict__ alo,
                                                   const float* __restrict__ bias) {
    int wrp = threadIdx.x >> 5, lane = threadIdx.x & 31;
    int j = blockIdx.x * 8 + wrp;
    if (j >= NN) return;
    int beg = g_off[j], end = g_off[j + 1];
    float2 a0 = {0.f, 0.f}, a1 = {0.f, 0.f};
    int e = beg;
    for (; e + 2 <= end; e += 2) {
        int s0 = g_srcs[e], s1 = g_srcs[e + 1];
        float w0 = g_wsrt[e], w1 = g_wsrt[e + 1];
        uint32_t h0 = *(const uint32_t*)(shi + (size_t)s0 * 64 + lane * 2);
        uint32_t l0 = *(const uint32_t*)(slo + (size_t)s0 * 64 + lane * 2);
        uint32_t h1 = *(const uint32_t*)(shi + (size_t)s1 * 64 + lane * 2);
        uint32_t l1 = *(const uint32_t*)(slo + (size_t)s1 * 64 + lane * 2);
        float2 v0 = rec2(h0, l0), v1 = rec2(h1, l1);
        a0.x = fmaf(w0, v0.x, a0.x); a0.y = fmaf(w0, v0.y, a0.y);
        a1.x = fmaf(w1, v1.x, a1.x); a1.y = fmaf(w1, v1.y, a1.y);
    }
    if (e < end) {
        int s0 = g_srcs[e];
        float w0 = g_wsrt[e];
        uint32_t h0 = *(const uint32_t*)(shi + (size_t)s0 * 64 + lane * 2);
        uint32_t l0 = *(const uint32_t*)(slo + (size_t)s0 * 64 + lane * 2);
        float2 v0 = rec2(h0, l0);
        a0.x = fmaf(w0, v0.x, a0.x); a0.y = fmaf(w0, v0.y, a0.y);
    }
    uint32_t xh = *(const uint32_t*)(ahi + (size_t)j * 64 + lane * 2);
    uint32_t xl = *(const uint32_t*)(alo + (size_t)j * 64 + lane * 2);
    float2 ad = rec2(xh, xl);
    float v0 = a0.x + a1.x + ad.x + bias[2 * lane];
    float v1 = a0.y + a1.y + ad.y + bias[2 * lane + 1];
    float m = fmaxf(v0, v1);
#pragma unroll
    for (int o = 16; o; o >>= 1) m = fmaxf(m, __shfl_xor_sync(0xffffffffu, m, o));
    float s = expf(v0 - m) + expf(v1 - m);
#pragma unroll
    for (int o = 16; o; o >>= 1) s += __shfl_xor_sync(0xffffffffu, s, o);
    float l = m + logf(s);
    uint32_t hi, lo;
    split2(v0 - l, v1 - l, hi, lo);
    *(uint32_t*)(g_zhi + (size_t)j * 64 + lane * 2) = hi;
    *(uint32_t*)(g_zlo + (size_t)j * 64 + lane * 2) = lo;
}

// ---------------- tensor GEMM via mma.sync (inputs pre-split bf16 planes) ----------
// D[128 rows, 128 cols] = sum_{hop} A_hop[rows, CINH] @ Wt_hop^T
// MODE 0: o0 planes [row*128+c] = relu(D + addend? + bias)
// MODE 1: o0 planes [row*64+c] (c<64), o1 planes [row*64+(c-64)] (c>=64), raw
template <int CINH, int NHOPS, int MODE>
__global__ __launch_bounds__(256)
void k_mma(const __nv_bfloat16* __restrict__ A0h, const __nv_bfloat16* __restrict__ A0l,
           const __nv_bfloat16* __restrict__ A1h, const __nv_bfloat16* __restrict__ A1l,
           const __nv_bfloat16* __restrict__ A2h, const __nv_bfloat16* __restrict__ A2l,
           const __nv_bfloat16* __restrict__ A3h, const __nv_bfloat16* __restrict__ A3l,
           const __nv_bfloat16* __restrict__ Wt,
           const float* __restrict__ addend, const float* __restrict__ bias,
           __nv_bfloat16* __restrict__ o0h, __nv_bfloat16* __restrict__ o0l,
           __nv_bfloat16* __restrict__ o1h, __nv_bfloat16* __restrict__ o1l) {
    constexpr int ASTR = CINH + 8;   // padded stride (bf16 elems); conflict-free frags
    extern __shared__ __align__(16) char sm[];
    __nv_bfloat16* sAhi = (__nv_bfloat16*)sm;
    __nv_bfloat16* sAlo = sAhi + 128 * ASTR;
    __nv_bfloat16* sWhi = sAlo + 128 * ASTR;
    __nv_bfloat16* sWlo = sWhi + 128 * ASTR;

    int tid = threadIdx.x, wid = tid >> 5, lane = tid & 31;
    int wm = wid & 3, wn = wid >> 2;       // 4 m-tiles x 2 n-tiles of warps
    int grp = lane >> 2, tig = lane & 3;

    float acc[2][8][4];
#pragma unroll
    for (int i = 0; i < 2; i++)
#pragma unroll
        for (int j = 0; j < 8; j++)
#pragma unroll
            for (int q = 0; q < 4; q++) acc[i][j][q] = 0.f;

    const __nv_bfloat16* Ahs[4] = {A0h, A1h, A2h, A3h};
    const __nv_bfloat16* Als[4] = {A0l, A1l, A2l, A3l};
    int row0 = blockIdx.x * 128;
    constexpr int KQ8 = CINH / 8;

    for (int h = 0; h < NHOPS; h++) {
        if (h) __syncthreads();
        // --- fill A planes (pure copies) ---
        const __nv_bfloat16* Ah = Ahs[h];
        const __nv_bfloat16* Al = Als[h];
        for (int u = tid; u < 128 * KQ8; u += 256) {
            int r = u / KQ8;
            int k8 = (u - r * KQ8) * 8;
            int grow = row0 + r;
            uint4 hv, lv;
            if (grow < NN) {
                hv = *(const uint4*)(Ah + (size_t)grow * CINH + k8);
                lv = *(const uint4*)(Al + (size_t)grow * CINH + k8);
            } else {
                hv = make_uint4(0, 0, 0, 0);
                lv = make_uint4(0, 0, 0, 0);
            }
            *(uint4*)(sAhi + r * ASTR + k8) = hv;
            *(uint4*)(sAlo + r * ASTR + k8) = lv;
        }
        // --- fill W (bf16 copy) ---
        for (int u = tid; u < 2 * 128 * KQ8; u += 256) {
            int s = u / (128 * KQ8);
            int rem = u - s * 128 * KQ8;
            int n = rem / KQ8;
            int k8 = (rem - n * KQ8) * 8;
            uint4 vv = *(const uint4*)(Wt + ((size_t)((h * 2 + s) * 128 + n)) * CINH + k8);
            *(uint4*)((s ? sWlo : sWhi) + n * ASTR + k8) = vv;
        }
        __syncthreads();

        // --- 3 split passes over full K ---
#pragma unroll
        for (int pass = 0; pass < 3; pass++) {
            const __nv_bfloat16* Ab = (pass == 2) ? sAlo : sAhi;
            const __nv_bfloat16* Wb = (pass == 1) ? sWlo : sWhi;
#pragma unroll
            for (int k8 = 0; k8 < CINH / 16; k8++) {
                uint32_t a[2][4];
                const __nv_bfloat16* ab = Ab + (wm * 32 + grp) * ASTR + k8 * 16 + 2 * tig;
#pragma unroll
                for (int ms = 0; ms < 2; ms++) {
                    const __nv_bfloat16* p = ab + ms * 16 * ASTR;
                    a[ms][0] = *(const uint32_t*)p;
                    a[ms][1] = *(const uint32_t*)(p + 8 * ASTR);
                    a[ms][2] = *(const uint32_t*)(p + 8);
                    a[ms][3] = *(const uint32_t*)(p + 8 * ASTR + 8);
                }
                const __nv_bfloat16* bb = Wb + (wn * 64 + grp) * ASTR + k8 * 16 + 2 * tig;
#pragma unroll
                for (int n8 = 0; n8 < 8; n8++) {
                    uint32_t b0 = *(const uint32_t*)(bb + n8 * 8 * ASTR);
                    uint32_t b1 = *(const uint32_t*)(bb + n8 * 8 * ASTR + 8);
                    mma16816(acc[0][n8], a[0], b0, b1);
                    mma16816(acc[1][n8], a[1], b0, b1);
                }
            }
        }
    }

    // --- epilogue ---
#pragma unroll
    for (int ms = 0; ms < 2; ms++) {
        int r0 = row0 + wm * 32 + ms * 16 + grp;
        int r1 = r0 + 8;
#pragma unroll
        for (int n8 = 0; n8 < 8; n8++) {
            int cb = wn * 64 + n8 * 8 + 2 * tig;
            float* d = acc[ms][n8];
            if constexpr (MODE == 0) {
                float b0v = __ldg(bias + cb), b1v = __ldg(bias + cb + 1);
                if (r0 < NN) {
                    float v0 = d[0] + b0v, v1 = d[1] + b1v;
                    if (addend) {
                        float2 ad = *(const float2*)(addend + (size_t)r0 * 128 + cb);
                        v0 += ad.x; v1 += ad.y;
                    }
                    uint32_t hi, lo;
                    split2(fmaxf(v0, 0.f), fmaxf(v1, 0.f), hi, lo);
                    *(uint32_t*)(o0h + (size_t)r0 * 128 + cb) = hi;
                    *(uint32_t*)(o0l + (size_t)r0 * 128 + cb) = lo;
                }
                if (r1 < NN) {
                    float v0 = d[2] + b0v, v1 = d[3] + b1v;
                    if (addend) {
                        float2 ad = *(const float2*)(addend + (size_t)r1 * 128 + cb);
                        v0 += ad.x; v1 += ad.y;
                    }
                    uint32_t hi, lo;
                    split2(fmaxf(v0, 0.f), fmaxf(v1, 0.f), hi, lo);
                    *(uint32_t*)(o0h + (size_t)r1 * 128 + cb) = hi;
                    *(uint32_t*)(o0l + (size_t)r1 * 128 + cb) = lo;
                }
            } else {
                __nv_bfloat16* oph = wn ? o1h : o0h;
                __nv_bfloat16* opl = wn ? o1l : o0l;
                int cc = n8 * 8 + 2 * tig;
                if (r0 < NN) {
                    uint32_t hi, lo;
                    split2(d[0], d[1], hi, lo);
                    *(uint32_t*)(oph + (size_t)r0 * 64 + cc) = hi;
                    *(uint32_t*)(opl + (size_t)r0 * 64 + cc) = lo;
                }
                if (r1 < NN) {
                    uint32_t hi, lo;
                    split2(d[2], d[3], hi, lo);
                    *(uint32_t*)(oph + (size_t)r1 * 64 + cc) = hi;
                    *(uint32_t*)(opl + (size_t)r1 * 64 + cc) = lo;
                }
            }
        }
    }
}

// ---------------- down MLP + output write ----------------
__global__ __launch_bounds__(256) void k_down(float* __restrict__ out,
                                              const float* __restrict__ w1, const float* __restrict__ b1,
                                              const float* __restrict__ w2, const float* __restrict__ b2) {
    int wrp = threadIdx.x >> 5, lane = threadIdx.x & 31;
    int j = blockIdx.x * 8 + wrp;
    if (j >= NN) return;
    float z0 = __bfloat162float(g_zhi[j * 64 + lane]) + __bfloat162float(g_zlo[j * 64 + lane]);
    float z1 = __bfloat162float(g_zhi[j * 64 + 32 + lane]) + __bfloat162float(g_zlo[j * 64 + 32 + lane]);
    out[NN + j * 64 + lane] = z0;
    out[NN + j * 64 + 32 + lane] = z1;
    float d = z0 * w1[lane] + z1 * w1[32 + lane];
#pragma unroll
    for (int o = 16; o; o >>= 1) d += __shfl_xor_sync(0xffffffffu, d, o);
    if (lane == 0) out[j] = gelu_exact(d + b1[0]) * w2[0] + b2[0];
}

// ---------------- host orchestration ----------------
extern "C" void kernel_launch(void* const* d_in, const int* in_sizes, int n_in,
                              void* d_out, int out_size) {
    const float* x      = (const float*)d_in[0];
    const float* pos    = (const float*)d_in[1];
    const float* ea     = (const float*)d_in[2];
    const float* up_w1  = (const float*)d_in[3];
    const float* up_b1  = (const float*)d_in[4];
    const float* up_w2  = (const float*)d_in[5];
    const float* up_b2  = (const float*)d_in[6];
    const float* c1_w   = (const float*)d_in[7];
    const float* c1_b   = (const float*)d_in[8];
    const float* c2_w   = (const float*)d_in[9];
    const float* c2_b   = (const float*)d_in[10];
    const float* c3_w   = (const float*)d_in[11];
    const float* c3_b   = (const float*)d_in[12];
    const float* dw1    = (const float*)d_in[13];
    const float* db1    = (const float*)d_in[14];
    const float* dw2    = (const float*)d_in[15];
    const float* db2    = (const float*)d_in[16];
    const int*   ei     = (const int*)d_in[17];
    const int* row = ei;
    const int* col = ei + EE;

    __nv_bfloat16 *zhi, *zlo, *hhi, *hlo;
    __nv_bfloat16 *p1hi, *p1lo, *p2hi, *p2lo, *p3hi, *p3lo;
    __nv_bfloat16 *y0hi, *y0lo, *y1hi, *y1lo, *y2hi, *y2lo, *y3hi, *y3lo;
    __nv_bfloat16 *wt1, *wt2, *wt3;
    float *pp1, *pp2, *pp3, *posacc;
    cudaGetSymbolAddress((void**)&zhi,  g_zhi);  cudaGetSymbolAddress((void**)&zlo,  g_zlo);
    cudaGetSymbolAddress((void**)&hhi,  g_hhi);  cudaGetSymbolAddress((void**)&hlo,  g_hlo);
    cudaGetSymbolAddress((void**)&p1hi, g_p1hi); cudaGetSymbolAddress((void**)&p1lo, g_p1lo);
    cudaGetSymbolAddress((void**)&p2hi, g_p2hi); cudaGetSymbolAddress((void**)&p2lo, g_p2lo);
    cudaGetSymbolAddress((void**)&p3hi, g_p3hi); cudaGetSymbolAddress((void**)&p3lo, g_p3lo);
    cudaGetSymbolAddress((void**)&y0hi, g_y0hi); cudaGetSymbolAddress((void**)&y0lo, g_y0lo);
    cudaGetSymbolAddress((void**)&y1hi, g_y1hi); cudaGetSymbolAddress((void**)&y1lo, g_y1lo);
    cudaGetSymbolAddress((void**)&y2hi, g_y2hi); cudaGetSymbolAddress((void**)&y2lo, g_y2lo);
    cudaGetSymbolAddress((void**)&y3hi, g_y3hi); cudaGetSymbolAddress((void**)&y3lo, g_y3lo);
    cudaGetSymbolAddress((void**)&pp1,  g_pp1);  cudaGetSymbolAddress((void**)&pp2,  g_pp2);
    cudaGetSymbolAddress((void**)&pp3,  g_pp3);  cudaGetSymbolAddress((void**)&posacc, g_posacc);
    cudaGetSymbolAddress((void**)&wt1,  g_wt1);
    cudaGetSymbolAddress((void**)&wt2,  g_wt2);
    cudaGetSymbolAddress((void**)&wt3,  g_wt3);

    const int SM64  = 4 * 128 * (64 + 8) * 2;    // 73728
    const int SM128 = 4 * 128 * (128 + 8) * 2;   // 139264
    cudaFuncSetAttribute((const void*)k_mma<64, 4, 0>,  cudaFuncAttributeMaxDynamicSharedMemorySize, SM64);
    cudaFuncSetAttribute((const void*)k_mma<128, 4, 0>, cudaFuncAttributeMaxDynamicSharedMemorySize, SM128);
    cudaFuncSetAttribute((const void*)k_mma<128, 1, 1>, cudaFuncAttributeMaxDynamicSharedMemorySize, SM128);

    const int GN = (NN + 255) / 256;
    const int GE = (EE + 255) / 256;
    const int GW = (NN + 7) / 8;
    const int GT = (NN + 127) / 128;
    const int GP = (NN * HID + 255) / 256;

    // --- graph setup ---
    k_zero<<<GN, 256>>>();
    k_hist<<<GE, 256>>>(col, ea);
    k_dinv<<<GN, 256>>>();
    k_scan<<<1, 1024>>>();
    k_cursor<<<GN, 256>>>();
    k_scatter<<<GE, 256>>>(row, col, ea);

    // --- weight prep (bf16 hi/lo, transposed) ---
    k_wprep1<<<(4 * 128 * 64 + 255) / 256, 256>>>(c1_w);
    k_wprep2<<<(4 * 128 * 128 + 255) / 256, 256>>>(c2_w);
    k_wprep3<<<(2 * 128 * 128 + 255) / 256, 256>>>(c3_w);

    // --- iteration-invariant pos hops + posacc ---
    k_prop3<<<GN, 256>>>(pp1, pos);
    k_prop3<<<GN, 256>>>(pp2, pp1);
    k_prop3<<<GN, 256>>>(pp3, pp2);
    k_posacc<<<GP, 256>>>(pos, c1_w);

    // --- up MLP -> z0 planes ---
    k_up<<<(NN + 3) / 4, 256>>>(x, up_w1, up_b1, up_w2, up_b2);

    // --- 21 gnn applications ---
    for (int it = 0; it < 21; it++) {
        // tag1: hops on z (64ch planes), tensor GEMM (+posacc, relu) -> h planes
        k_prop64<<<GW, 256>>>(p1hi, p1lo, zhi, zlo);
        k_prop64<<<GW, 256>>>(p2hi, p2lo, p1hi, p1lo);
        k_prop64<<<GW, 256>>>(p3hi, p3lo, p2hi, p2lo);
        k_mma<64, 4, 0><<<GT, 256, SM64>>>(zhi, zlo, p1hi, p1lo, p2hi, p2lo, p3hi, p3lo,
                                           wt1, posacc, c1_b, hhi, hlo, nullptr, nullptr);

        // tag2: hops on h (128ch planes), tensor GEMM (relu) -> h planes
        k_prop128<<<GW, 256>>>(p1hi, p1lo, hhi, hlo);
        k_prop128<<<GW, 256>>>(p2hi, p2lo, p1hi, p1lo);
        k_prop128<<<GW, 256>>>(p3hi, p3lo, p2hi, p2lo);
        k_mma<128, 4, 0><<<GT, 256, SM128>>>(hhi, hlo, p1hi, p1lo, p2hi, p2lo, p3hi, p3lo,
                                             wt2, nullptr, c2_b, hhi, hlo, nullptr, nullptr);

        // tag3: paired tensor GEMMs first, then 64ch prop chain
        k_mma<128, 1, 1><<<GT, 256, SM128>>>(hhi, hlo, hhi, hlo, hhi, hlo, hhi, hlo,
                                             wt3, nullptr, nullptr, y0hi, y0lo, y1hi, y1lo);
        k_mma<128, 1, 1><<<GT, 256, SM128>>>(hhi, hlo, hhi, hlo, hhi, hlo, hhi, hlo,
                                             wt3 + 2 * 128 * 128, nullptr, nullptr, y2hi, y2lo, y3hi, y3lo);
        k_propadd64<<<GW, 256>>>(p1hi, p1lo, y3hi, y3lo, y2hi, y2lo);   // t1 = P y3 + y2
        k_propadd64<<<GW, 256>>>(p2hi, p2lo, p1hi, p1lo, y1hi, y1lo);   // t2 = P t1 + y1
        k_proplogsm<<<GW, 256>>>(p2hi, p2lo, y0hi, y0lo, c3_b);         // z = logsm(P t2 + y0 + b)
    }

    // --- down MLP + write (out, z_star) ---
    k_down<<<GW, 256>>>((float*)d_out, dw1, db1, dw2, db2);

    (void)in_sizes; (void)n_in; (void)out_size;
}

// round 10
// speedup vs baseline: 1.1538x; 1.1538x over previous
#include <cuda_runtime.h>
#include <cuda_bf16.h>
#include <math.h>
#include <stdint.h>

#define NN 50000
#define EE 800000
#define EMB 64
#define HID 128

// ---------------- scratch (device globals; no allocation allowed) ----------------
__device__ float g_deg[NN];
__device__ float g_dinv[NN];
__device__ int   g_cnt[NN];
__device__ int   g_off[NN + 1];
__device__ int   g_cur[NN];
__device__ int   g_bsum[64];
__device__ int   g_srcs[EE];
__device__ float g_wsrt[EE];

__device__ __align__(16) float g_z[NN * EMB];       // state z
__device__ __align__(16) float g_h[NN * HID];       // tag output (relu'd)
__device__ __align__(16) float g_p1[NN * HID];      // hop buffers
__device__ __align__(16) float g_p2[NN * HID];
__device__ __align__(16) float g_p3[NN * HID];
__device__ __align__(16) float g_y0[NN * EMB];      // tag3 per-k GEMM outputs
__device__ __align__(16) float g_y1[NN * EMB];
__device__ __align__(16) float g_y2[NN * EMB];
__device__ __align__(16) float g_y3[NN * EMB];
__device__ __align__(16) float g_pp1[NN * 3];
__device__ __align__(16) float g_pp2[NN * 3];
__device__ __align__(16) float g_pp3[NN * 3];
__device__ __align__(16) float g_posacc[NN * HID];

// pre-split, pre-transposed weights: [hop][s=hi/lo][n(128)][k(CINH)] bf16
__device__ __align__(16) __nv_bfloat16 g_wt1[4 * 2 * 128 * 64];
__device__ __align__(16) __nv_bfloat16 g_wt2[4 * 2 * 128 * 128];
__device__ __align__(16) __nv_bfloat16 g_wt3[2 * 2 * 128 * 128];

__device__ __forceinline__ float gelu_exact(float x) {
    return 0.5f * x * (1.0f + erff(x * 0.70710678118654752f));
}

// fast fp32 pair -> packed bf16 hi/lo (cvt.rn.bf16x2 + shift reconstruction)
__device__ __forceinline__ void split2f(float x, float y, uint32_t& hi, uint32_t& lo) {
    asm("cvt.rn.bf16x2.f32 %0, %1, %2;" : "=r"(hi) : "f"(y), "f"(x));   // hi half=bf16(y), lo half=bf16(x)
    float h0 = __uint_as_float(hi << 16);
    float h1 = __uint_as_float(hi & 0xFFFF0000u);
    float r0 = x - h0, r1 = y - h1;
    asm("cvt.rn.bf16x2.f32 %0, %1, %2;" : "=r"(lo) : "f"(r1), "f"(r0));
}

// ---------------- mma.sync helper (bf16, m16n8k16, fp32 acc) ----------------
__device__ __forceinline__ void mma16816(float* d, const uint32_t* a, uint32_t b0, uint32_t b1) {
    asm volatile(
        "mma.sync.aligned.m16n8k16.row.col.f32.bf16.bf16.f32 "
        "{%0,%1,%2,%3}, {%4,%5,%6,%7}, {%8,%9}, {%0,%1,%2,%3};"
        : "+f"(d[0]), "+f"(d[1]), "+f"(d[2]), "+f"(d[3])
        : "r"(a[0]), "r"(a[1]), "r"(a[2]), "r"(a[3]), "r"(b0), "r"(b1));
}

// ---------------- setup kernels ----------------
__global__ void k_zero() {
    int i = blockIdx.x * blockDim.x + threadIdx.x;
    if (i < NN) { g_deg[i] = 0.f; g_cnt[i] = 0; }
}

__global__ void k_hist(const int* __restrict__ col, const float* __restrict__ ea) {
    int e = blockIdx.x * blockDim.x + threadIdx.x;
    if (e < EE) {
        int c = col[e];
        atomicAdd(&g_deg[c], ea[e]);
        atomicAdd(&g_cnt[c], 1);
    }
}

__global__ void k_dinv() {
    int i = blockIdx.x * blockDim.x + threadIdx.x;
    if (i < NN) {
        float d = g_deg[i];
        g_dinv[i] = (d > 0.f) ? rsqrtf(d) : 0.f;
    }
}

// hierarchical scan: block-local exclusive + block sums
__global__ void k_scan1() {
    __shared__ int sh[1024];
    int blk = blockIdx.x, tid = threadIdx.x;
    int i = blk * 1024 + tid;
    int v = (i < NN) ? g_cnt[i] : 0;
    sh[tid] = v;
    __syncthreads();
    for (int ofs = 1; ofs < 1024; ofs <<= 1) {
        int t = (tid >= ofs) ? sh[tid - ofs] : 0;
        __syncthreads();
        sh[tid] += t;
        __syncthreads();
    }
    if (i < NN) g_off[i] = sh[tid] - v;
    if (tid == 1023) g_bsum[blk] = sh[1023];
}

__global__ void k_scan2(int nblk) {
    __shared__ int sh[64];
    int tid = threadIdx.x;
    int v = (tid < nblk) ? g_bsum[tid] : 0;
    sh[tid] = v;
    __syncthreads();
    for (int ofs = 1; ofs < 64; ofs <<= 1) {
        int t = (tid >= ofs) ? sh[tid - ofs] : 0;
        __syncthreads();
        sh[tid] += t;
        __syncthreads();
    }
    g_bsum[tid] = sh[tid] - v;   // exclusive
}

__global__ void k_scan3() {
    int i = blockIdx.x * blockDim.x + threadIdx.x;
    if (i < NN) {
        int o = g_off[i] + g_bsum[i >> 10];
        g_off[i] = o;
        g_cur[i] = o;
    }
    if (i == 0) g_off[NN] = EE;
}

__global__ void k_scatter(const int* __restrict__ row, const int* __restrict__ col,
                          const float* __restrict__ ea) {
    int e = blockIdx.x * blockDim.x + threadIdx.x;
    if (e < EE) {
        int r = row[e], c = col[e];
        int p = atomicAdd(&g_cur[c], 1);
        g_srcs[p] = r;
        g_wsrt[p] = g_dinv[r] * ea[e] * g_dinv[c];
    }
}

// ---------------- weight prep: transpose + bf16 hi/lo split ----------------
__device__ __forceinline__ void split_store(__nv_bfloat16* hi, __nv_bfloat16* lo, float w) {
    __nv_bfloat16 hb = __float2bfloat16(w);
    *hi = hb;
    *lo = __float2bfloat16(w - __bfloat162float(hb));
}

__global__ void k_wprep1(const float* __restrict__ c1w) {   // [4][67][128] -> g_wt1 [4][2][128][64]
    int idx = blockIdx.x * blockDim.x + threadIdx.x;
    if (idx >= 4 * 128 * 64) return;
    int hop = idx / (128 * 64);
    int r = idx - hop * 128 * 64;
    int n = r >> 6, k = r & 63;
    float w = c1w[hop * 67 * 128 + k * 128 + n];
    size_t b = ((size_t)(hop * 2) * 128 + n) * 64 + k;
    split_store(&g_wt1[b], &g_wt1[b + 128 * 64], w);
}

__global__ void k_wprep2(const float* __restrict__ c2w) {   // [4][128][128] -> g_wt2 [4][2][128][128]
    int idx = blockIdx.x * blockDim.x + threadIdx.x;
    if (idx >= 4 * 128 * 128) return;
    int hop = idx / (128 * 128);
    int r = idx - hop * 128 * 128;
    int n = r >> 7, k = r & 127;
    float w = c2w[hop * 128 * 128 + k * 128 + n];
    size_t b = ((size_t)(hop * 2) * 128 + n) * 128 + k;
    split_store(&g_wt2[b], &g_wt2[b + 128 * 128], w);
}

__global__ void k_wprep3(const float* __restrict__ c3w) {   // [4][128][64] -> g_wt3 [2 pairs][2][128][128]
    int idx = blockIdx.x * blockDim.x + threadIdx.x;
    if (idx >= 2 * 128 * 128) return;
    int pair = idx / (128 * 128);
    int r = idx - pair * 128 * 128;
    int n = r >> 7, k = r & 127;
    int wk = pair * 2 + (n >> 6);
    int nn = n & 63;
    float w = c3w[wk * 128 * 64 + k * 64 + nn];
    size_t b = ((size_t)(pair * 2) * 128 + n) * 128 + k;
    split_store(&g_wt3[b], &g_wt3[b + 128 * 128], w);
}

// ---------------- pos hops + posacc ----------------
__global__ void k_prop3(float* __restrict__ dst, const float* __restrict__ src) {
    int j = blockIdx.x * blockDim.x + threadIdx.x;
    if (j >= NN) return;
    int beg = g_off[j], end = g_off[j + 1];
    float a0 = 0.f, a1 = 0.f, a2 = 0.f;
    for (int e = beg; e < end; e++) {
        int s = g_srcs[e];
        float w = g_wsrt[e];
        a0 += w * src[s * 3 + 0];
        a1 += w * src[s * 3 + 1];
        a2 += w * src[s * 3 + 2];
    }
    dst[j * 3 + 0] = a0; dst[j * 3 + 1] = a1; dst[j * 3 + 2] = a2;
}

__global__ void k_posacc(const float* __restrict__ pos, const float* __restrict__ c1w) {
    int idx = blockIdx.x * blockDim.x + threadIdx.x;
    if (idx >= NN * HID) return;
    int n = idx >> 7, c = idx & 127;
    const float* pps[4] = {pos, g_pp1, g_pp2, g_pp3};
    float acc = 0.f;
#pragma unroll
    for (int k = 0; k < 4; k++) {
        const float* pp = pps[k] + n * 3;
        const float* wr = c1w + k * 67 * 128 + 64 * 128 + c;
        acc += pp[0] * wr[0] + pp[1] * wr[128] + pp[2] * wr[256];
    }
    g_posacc[idx] = acc;
}

// ---------------- up MLP ----------------
__global__ __launch_bounds__(256) void k_up(const float* __restrict__ x,
                                            const float* __restrict__ w1, const float* __restrict__ b1,
                                            const float* __restrict__ w2, const float* __restrict__ b2) {
    __shared__ float sw2[64 * 64];
    __shared__ float hid[4][64];
    int tid = threadIdx.x;
#pragma unroll
    for (int i = 0; i < 16; i++) sw2[tid * 16 + i] = w2[tid * 16 + i];
    int local = tid >> 6;
    int c = tid & 63;
    int node = blockIdx.x * 4 + local;
    float h = 0.f;
    if (node < NN) {
        h = b1[c];
#pragma unroll
        for (int i = 0; i < 4; i++) h += x[node * 4 + i] * w1[i * 64 + c];
        h = gelu_exact(h);
    }
    hid[local][c] = h;
    __syncthreads();
    if (node < NN) {
        float o = b2[c];
#pragma unroll
        for (int j = 0; j < 64; j++) o += hid[local][j] * sw2[j * 64 + c];
        g_z[node * 64 + c] = o;
    }
}

// ---------------- propagation kernels (CSR, warp per node) ----------------
__global__ __launch_bounds__(256) void k_prop64(float* __restrict__ dst, const float* __restrict__ src) {
    int wrp = threadIdx.x >> 5, lane = threadIdx.x & 31;
    int j = blockIdx.x * 8 + wrp;
    if (j >= NN) return;
    int beg = g_off[j], end = g_off[j + 1];
    float2 a0 = {0.f, 0.f}, a1 = {0.f, 0.f};
    int e = beg;
    for (; e + 2 <= end; e += 2) {
        int s0 = g_srcs[e], s1 = g_srcs[e + 1];
        float w0 = g_wsrt[e], w1 = g_wsrt[e + 1];
        float2 v0 = *(const float2*)(src + (size_t)s0 * 64 + lane * 2);
        float2 v1 = *(const float2*)(src + (size_t)s1 * 64 + lane * 2);
        a0.x = fmaf(w0, v0.x, a0.x); a0.y = fmaf(w0, v0.y, a0.y);
        a1.x = fmaf(w1, v1.x, a1.x); a1.y = fmaf(w1, v1.y, a1.y);
    }
    if (e < end) {
        int s0 = g_srcs[e];
        float w0 = g_wsrt[e];
        float2 v0 = *(const float2*)(src + (size_t)s0 * 64 + lane * 2);
        a0.x = fmaf(w0, v0.x, a0.x); a0.y = fmaf(w0, v0.y, a0.y);
    }
    float2 r; r.x = a0.x + a1.x; r.y = a0.y + a1.y;
    *(float2*)(dst + (size_t)j * 64 + lane * 2) = r;
}

__global__ __launch_bounds__(256) void k_prop128(float* __restrict__ dst, const float* __restrict__ src) {
    int wrp = threadIdx.x >> 5, lane = threadIdx.x & 31;
    int j = blockIdx.x * 8 + wrp;
    if (j >= NN) return;
    int beg = g_off[j], end = g_off[j + 1];
    float4 a0 = {0.f,0.f,0.f,0.f}, a1 = {0.f,0.f,0.f,0.f};
    int e = beg;
    for (; e + 2 <= end; e += 2) {
        int s0 = g_srcs[e], s1 = g_srcs[e + 1];
        float w0 = g_wsrt[e], w1 = g_wsrt[e + 1];
        float4 v0 = *(const float4*)(src + (size_t)s0 * 128 + lane * 4);
        float4 v1 = *(const float4*)(src + (size_t)s1 * 128 + lane * 4);
        a0.x = fmaf(w0, v0.x, a0.x); a0.y = fmaf(w0, v0.y, a0.y);
        a0.z = fmaf(w0, v0.z, a0.z); a0.w = fmaf(w0, v0.w, a0.w);
        a1.x = fmaf(w1, v1.x, a1.x); a1.y = fmaf(w1, v1.y, a1.y);
        a1.z = fmaf(w1, v1.z, a1.z); a1.w = fmaf(w1, v1.w, a1.w);
    }
    if (e < end) {
        int s0 = g_srcs[e];
        float w0 = g_wsrt[e];
        float4 v0 = *(const float4*)(src + (size_t)s0 * 128 + lane * 4);
        a0.x = fmaf(w0, v0.x, a0.x); a0.y = fmaf(w0, v0.y, a0.y);
        a0.z = fmaf(w0, v0.z, a0.z); a0.w = fmaf(w0, v0.w, a0.w);
    }
    float4 r;
    r.x = a0.x + a1.x; r.y = a0.y + a1.y; r.z = a0.z + a1.z; r.w = a0.w + a1.w;
    *(float4*)(dst + (size_t)j * 128 + lane * 4) = r;
}

__global__ __launch_bounds__(256) void k_propadd64(float* __restrict__ dst, const float* __restrict__ src,
                                                   const float* __restrict__ add) {
    int wrp = threadIdx.x >> 5, lane = threadIdx.x & 31;
    int j = blockIdx.x * 8 + wrp;
    if (j >= NN) return;
    int beg = g_off[j], end = g_off[j + 1];
    float2 a0 = {0.f, 0.f}, a1 = {0.f, 0.f};
    int e = beg;
    for (; e + 2 <= end; e += 2) {
        int s0 = g_srcs[e], s1 = g_srcs[e + 1];
        float w0 = g_wsrt[e], w1 = g_wsrt[e + 1];
        float2 v0 = *(const float2*)(src + (size_t)s0 * 64 + lane * 2);
        float2 v1 = *(const float2*)(src + (size_t)s1 * 64 + lane * 2);
        a0.x = fmaf(w0, v0.x, a0.x); a0.y = fmaf(w0, v0.y, a0.y);
        a1.x = fmaf(w1, v1.x, a1.x); a1.y = fmaf(w1, v1.y, a1.y);
    }
    if (e < end) {
        int s0 = g_srcs[e];
        float w0 = g_wsrt[e];
        float2 v0 = *(const float2*)(src + (size_t)s0 * 64 + lane * 2);
        a0.x = fmaf(w0, v0.x, a0.x); a0.y = fmaf(w0, v0.y, a0.y);
    }
    float2 ad = *(const float2*)(add + (size_t)j * 64 + lane * 2);
    float2 r; r.x = a0.x + a1.x + ad.x; r.y = a0.y + a1.y + ad.y;
    *(float2*)(dst + (size_t)j * 64 + lane * 2) = r;
}

__global__ __launch_bounds__(256) void k_proplogsm(const float* __restrict__ src,
                                                   const float* __restrict__ add,
                                                   const float* __restrict__ bias) {
    int wrp = threadIdx.x >> 5, lane = threadIdx.x & 31;
    int j = blockIdx.x * 8 + wrp;
    if (j >= NN) return;
    int beg = g_off[j], end = g_off[j + 1];
    float2 a0 = {0.f, 0.f}, a1 = {0.f, 0.f};
    int e = beg;
    for (; e + 2 <= end; e += 2) {
        int s0 = g_srcs[e], s1 = g_srcs[e + 1];
        float w0 = g_wsrt[e], w1 = g_wsrt[e + 1];
        float2 v0 = *(const float2*)(src + (size_t)s0 * 64 + lane * 2);
        float2 v1 = *(const float2*)(src + (size_t)s1 * 64 + lane * 2);
        a0.x = fmaf(w0, v0.x, a0.x); a0.y = fmaf(w0, v0.y, a0.y);
        a1.x = fmaf(w1, v1.x, a1.x); a1.y = fmaf(w1, v1.y, a1.y);
    }
    if (e < end) {
        int s0 = g_srcs[e];
        float w0 = g_wsrt[e];
        float2 v0 = *(const float2*)(src + (size_t)s0 * 64 + lane * 2);
        a0.x = fmaf(w0, v0.x, a0.x); a0.y = fmaf(w0, v0.y, a0.y);
    }
    float2 ad = *(const float2*)(add + (size_t)j * 64 + lane * 2);
    float v0 = a0.x + a1.x + ad.x + bias[2 * lane];
    float v1 = a0.y + a1.y + ad.y + bias[2 * lane + 1];
    float m = fmaxf(v0, v1);
#pragma unroll
    for (int o = 16; o; o >>= 1) m = fmaxf(m, __shfl_xor_sync(0xffffffffu, m, o));
    float s = expf(v0 - m) + expf(v1 - m);
#pragma unroll
    for (int o = 16; o; o >>= 1) s += __shfl_xor_sync(0xffffffffu, s, o);
    float l = m + logf(s);
    g_z[j * 64 + 2 * lane]     = v0 - l;
    g_z[j * 64 + 2 * lane + 1] = v1 - l;
}

// ---------------- tensor GEMM via mma.sync (bf16 2-term split, fp32 acc) -----------
// D[128 rows, 128 cols] = sum_{hop} A_hop[rows, CINH] @ Wt_hop^T
// out0[row*128+c] = relu(D + addend? + bias)
template <int CINH, int NHOPS>
__global__ __launch_bounds__(256)
void k_mma(const float* __restrict__ A0, const float* __restrict__ A1,
           const float* __restrict__ A2, const float* __restrict__ A3,
           const __nv_bfloat16* __restrict__ Wt,
           const float* __restrict__ addend, const float* __restrict__ bias,
           float* __restrict__ out0) {
    constexpr int ASTR = CINH + 8;
    extern __shared__ __align__(16) char sm[];
    __nv_bfloat16* sAhi = (__nv_bfloat16*)sm;
    __nv_bfloat16* sAlo = sAhi + 128 * ASTR;
    __nv_bfloat16* sWhi = sAlo + 128 * ASTR;
    __nv_bfloat16* sWlo = sWhi + 128 * ASTR;

    int tid = threadIdx.x, wid = tid >> 5, lane = tid & 31;
    int wm = wid & 3, wn = wid >> 2;
    int grp = lane >> 2, tig = lane & 3;

    float acc[2][8][4];
#pragma unroll
    for (int i = 0; i < 2; i++)
#pragma unroll
        for (int j = 0; j < 8; j++)
#pragma unroll
            for (int q = 0; q < 4; q++) acc[i][j][q] = 0.f;

    const float* As[4] = {A0, A1, A2, A3};
    int row0 = blockIdx.x * 128;
    constexpr int KQ4 = CINH / 4;
    constexpr int KQ8 = CINH / 8;

    for (int h = 0; h < NHOPS; h++) {
        if (h) __syncthreads();
        // --- fill A (fp32 -> bf16 hi/lo, fast split) ---
        const float* Ah = As[h];
        for (int u = tid; u < 128 * KQ4; u += 256) {
            int r = u / KQ4;
            int k4 = (u - r * KQ4) * 4;
            int grow = row0 + r;
            float4 f;
            if (grow < NN) f = *(const float4*)(Ah + (size_t)grow * CINH + k4);
            else { f.x = f.y = f.z = f.w = 0.f; }
            uint32_t hp0, lp0, hp1, lp1;
            split2f(f.x, f.y, hp0, lp0);
            split2f(f.z, f.w, hp1, lp1);
            *(uint2*)(sAhi + r * ASTR + k4) = make_uint2(hp0, hp1);
            *(uint2*)(sAlo + r * ASTR + k4) = make_uint2(lp0, lp1);
        }
        // --- fill W (bf16 copy) ---
        for (int u = tid; u < 2 * 128 * KQ8; u += 256) {
            int s = u / (128 * KQ8);
            int rem = u - s * 128 * KQ8;
            int n = rem / KQ8;
            int k8 = (rem - n * KQ8) * 8;
            uint4 vv = *(const uint4*)(Wt + ((size_t)((h * 2 + s) * 128 + n)) * CINH + k8);
            *(uint4*)((s ? sWlo : sWhi) + n * ASTR + k8) = vv;
        }
        __syncthreads();

        // --- 3 split passes over full K ---
#pragma unroll
        for (int pass = 0; pass < 3; pass++) {
            const __nv_bfloat16* Ab = (pass == 2) ? sAlo : sAhi;
            const __nv_bfloat16* Wb = (pass == 1) ? sWlo : sWhi;
#pragma unroll
            for (int k8 = 0; k8 < CINH / 16; k8++) {
                uint32_t a[2][4];
                const __nv_bfloat16* ab = Ab + (wm * 32 + grp) * ASTR + k8 * 16 + 2 * tig;
#pragma unroll
                for (int ms = 0; ms < 2; ms++) {
                    const __nv_bfloat16* p = ab + ms * 16 * ASTR;
                    a[ms][0] = *(const uint32_t*)p;
                    a[ms][1] = *(const uint32_t*)(p + 8 * ASTR);
                    a[ms][2] = *(const uint32_t*)(p + 8);
                    a[ms][3] = *(const uint32_t*)(p + 8 * ASTR + 8);
                }
                const __nv_bfloat16* bb = Wb + (wn * 64 + grp) * ASTR + k8 * 16 + 2 * tig;
#pragma unroll
                for (int n8 = 0; n8 < 8; n8++) {
                    uint32_t b0 = *(const uint32_t*)(bb + n8 * 8 * ASTR);
                    uint32_t b1 = *(const uint32_t*)(bb + n8 * 8 * ASTR + 8);
                    mma16816(acc[0][n8], a[0], b0, b1);
                    mma16816(acc[1][n8], a[1], b0, b1);
                }
            }
        }
    }

    // --- epilogue: relu(D + addend? + bias) ---
#pragma unroll
    for (int ms = 0; ms < 2; ms++) {
        int r0 = row0 + wm * 32 + ms * 16 + grp;
        int r1 = r0 + 8;
#pragma unroll
        for (int n8 = 0; n8 < 8; n8++) {
            int cb = wn * 64 + n8 * 8 + 2 * tig;
            float* d = acc[ms][n8];
            float b0v = __ldg(bias + cb), b1v = __ldg(bias + cb + 1);
            if (r0 < NN) {
                float v0 = d[0] + b0v, v1 = d[1] + b1v;
                if (addend) {
                    float2 ad = *(const float2*)(addend + (size_t)r0 * 128 + cb);
                    v0 += ad.x; v1 += ad.y;
                }
                float2 o; o.x = fmaxf(v0, 0.f); o.y = fmaxf(v1, 0.f);
                *(float2*)(out0 + (size_t)r0 * 128 + cb) = o;
            }
            if (r1 < NN) {
                float v0 = d[2] + b0v, v1 = d[3] + b1v;
                if (addend) {
                    float2 ad = *(const float2*)(addend + (size_t)r1 * 128 + cb);
                    v0 += ad.x; v1 += ad.y;
                }
                float2 o; o.x = fmaxf(v0, 0.f); o.y = fmaxf(v1, 0.f);
                *(float2*)(out0 + (size_t)r1 * 128 + cb) = o;
            }
        }
    }
}

// ---------------- tag3 GEMM: one A fill, two W pair sets -> y0..y3 (raw) -----------
__global__ __launch_bounds__(256)
void k_mma3(const float* __restrict__ A, const __nv_bfloat16* __restrict__ Wt,
            float* __restrict__ y0, float* __restrict__ y1,
            float* __restrict__ y2, float* __restrict__ y3) {
    constexpr int CINH = 128;
    constexpr int ASTR = CINH + 8;
    extern __shared__ __align__(16) char sm[];
    __nv_bfloat16* sAhi = (__nv_bfloat16*)sm;
    __nv_bfloat16* sAlo = sAhi + 128 * ASTR;
    __nv_bfloat16* sWhi = sAlo + 128 * ASTR;
    __nv_bfloat16* sWlo = sWhi + 128 * ASTR;

    int tid = threadIdx.x, wid = tid >> 5, lane = tid & 31;
    int wm = wid & 3, wn = wid >> 2;
    int grp = lane >> 2, tig = lane & 3;
    int row0 = blockIdx.x * 128;
    constexpr int KQ4 = CINH / 4;
    constexpr int KQ8 = CINH / 8;

    // --- fill A once ---
    for (int u = tid; u < 128 * KQ4; u += 256) {
        int r = u / KQ4;
        int k4 = (u - r * KQ4) * 4;
        int grow = row0 + r;
        float4 f;
        if (grow < NN) f = *(const float4*)(A + (size_t)grow * CINH + k4);
        else { f.x = f.y = f.z = f.w = 0.f; }
        uint32_t hp0, lp0, hp1, lp1;
        split2f(f.x, f.y, hp0, lp0);
        split2f(f.z, f.w, hp1, lp1);
        *(uint2*)(sAhi + r * ASTR + k4) = make_uint2(hp0, hp1);
        *(uint2*)(sAlo + r * ASTR + k4) = make_uint2(lp0, lp1);
    }

    for (int set = 0; set < 2; set++) {
        // --- fill W planes for this pair ---
        const __nv_bfloat16* Wp = Wt + (size_t)set * 2 * 128 * CINH;
        for (int u = tid; u < 2 * 128 * KQ8; u += 256) {
            int s = u / (128 * KQ8);
            int rem = u - s * 128 * KQ8;
            int n = rem / KQ8;
            int k8 = (rem - n * KQ8) * 8;
            uint4 vv = *(const uint4*)(Wp + ((size_t)(s * 128 + n)) * CINH + k8);
            *(uint4*)((s ? sWlo : sWhi) + n * ASTR + k8) = vv;
        }
        __syncthreads();

        float acc[2][8][4];
#pragma unroll
        for (int i = 0; i < 2; i++)
#pragma unroll
            for (int j = 0; j < 8; j++)
#pragma unroll
                for (int q = 0; q < 4; q++) acc[i][j][q] = 0.f;

#pragma unroll
        for (int pass = 0; pass < 3; pass++) {
            const __nv_bfloat16* Ab = (pass == 2) ? sAlo : sAhi;
            const __nv_bfloat16* Wb = (pass == 1) ? sWlo : sWhi;
#pragma unroll
            for (int k8 = 0; k8 < CINH / 16; k8++) {
                uint32_t a[2][4];
                const __nv_bfloat16* ab = Ab + (wm * 32 + grp) * ASTR + k8 * 16 + 2 * tig;
#pragma unroll
                for (int ms = 0; ms < 2; ms++) {
                    const __nv_bfloat16* p = ab + ms * 16 * ASTR;
                    a[ms][0] = *(const uint32_t*)p;
                    a[ms][1] = *(const uint32_t*)(p + 8 * ASTR);
                    a[ms][2] = *(const uint32_t*)(p + 8);
                    a[ms][3] = *(const uint32_t*)(p + 8 * ASTR + 8);
                }
                const __nv_bfloat16* bb = Wb + (wn * 64 + grp) * ASTR + k8 * 16 + 2 * tig;
#pragma unroll
                for (int n8 = 0; n8 < 8; n8++) {
                    uint32_t b0 = *(const uint32_t*)(bb + n8 * 8 * ASTR);
                    uint32_t b1 = *(const uint32_t*)(bb + n8 * 8 * ASTR + 8);
                    mma16816(acc[0][n8], a[0], b0, b1);
                    mma16816(acc[1][n8], a[1], b0, b1);
                }
            }
        }

        // --- epilogue: raw writes to this set's pair ---
        float* oA = set ? y2 : y0;
        float* oB = set ? y3 : y1;
        float* op = wn ? oB : oA;
#pragma unroll
        for (int ms = 0; ms < 2; ms++) {
            int r0 = row0 + wm * 32 + ms * 16 + grp;
            int r1 = r0 + 8;
#pragma unroll
            for (int n8 = 0; n8 < 8; n8++) {
                int cc = n8 * 8 + 2 * tig;
                float* d = acc[ms][n8];
                if (r0 < NN) {
                    float2 o; o.x = d[0]; o.y = d[1];
                    *(float2*)(op + (size_t)r0 * 64 + cc) = o;
                }
                if (r1 < NN) {
                    float2 o; o.x = d[2]; o.y = d[3];
                    *(float2*)(op + (size_t)r1 * 64 + cc) = o;
                }
            }
        }
        __syncthreads();   // before next set overwrites W smem
    }
}

// ---------------- down MLP + output write ----------------
__global__ __launch_bounds__(256) void k_down(float* __restrict__ out,
                                              const float* __restrict__ w1, const float* __restrict__ b1,
                                              const float* __restrict__ w2, const float* __restrict__ b2) {
    int wrp = threadIdx.x >> 5, lane = threadIdx.x & 31;
    int j = blockIdx.x * 8 + wrp;
    if (j >= NN) return;
    float z0 = g_z[j * 64 + lane];
    float z1 = g_z[j * 64 + 32 + lane];
    out[NN + j * 64 + lane] = z0;
    out[NN + j * 64 + 32 + lane] = z1;
    float d = z0 * w1[lane] + z1 * w1[32 + lane];
#pragma unroll
    for (int o = 16; o; o >>= 1) d += __shfl_xor_sync(0xffffffffu, d, o);
    if (lane == 0) out[j] = gelu_exact(d + b1[0]) * w2[0] + b2[0];
}

// ---------------- host orchestration ----------------
extern "C" void kernel_launch(void* const* d_in, const int* in_sizes, int n_in,
                              void* d_out, int out_size) {
    const float* x      = (const float*)d_in[0];
    const float* pos    = (const float*)d_in[1];
    const float* ea     = (const float*)d_in[2];
    const float* up_w1  = (const float*)d_in[3];
    const float* up_b1  = (const float*)d_in[4];
    const float* up_w2  = (const float*)d_in[5];
    const float* up_b2  = (const float*)d_in[6];
    const float* c1_w   = (const float*)d_in[7];
    const float* c1_b   = (const float*)d_in[8];
    const float* c2_w   = (const float*)d_in[9];
    const float* c2_b   = (const float*)d_in[10];
    const float* c3_w   = (const float*)d_in[11];
    const float* c3_b   = (const float*)d_in[12];
    const float* dw1    = (const float*)d_in[13];
    const float* db1    = (const float*)d_in[14];
    const float* dw2    = (const float*)d_in[15];
    const float* db2    = (const float*)d_in[16];
    const int*   ei     = (const int*)d_in[17];
    const int* row = ei;
    const int* col = ei + EE;

    float *z, *h, *p1, *p2, *p3, *y0, *y1, *y2, *y3, *pp1, *pp2, *pp3, *posacc;
    __nv_bfloat16 *wt1, *wt2, *wt3;
    cudaGetSymbolAddress((void**)&z,      g_z);
    cudaGetSymbolAddress((void**)&h,      g_h);
    cudaGetSymbolAddress((void**)&p1,     g_p1);
    cudaGetSymbolAddress((void**)&p2,     g_p2);
    cudaGetSymbolAddress((void**)&p3,     g_p3);
    cudaGetSymbolAddress((void**)&y0,     g_y0);
    cudaGetSymbolAddress((void**)&y1,     g_y1);
    cudaGetSymbolAddress((void**)&y2,     g_y2);
    cudaGetSymbolAddress((void**)&y3,     g_y3);
    cudaGetSymbolAddress((void**)&pp1,    g_pp1);
    cudaGetSymbolAddress((void**)&pp2,    g_pp2);
    cudaGetSymbolAddress((void**)&pp3,    g_pp3);
    cudaGetSymbolAddress((void**)&posacc, g_posacc);
    cudaGetSymbolAddress((void**)&wt1,    g_wt1);
    cudaGetSymbolAddress((void**)&wt2,    g_wt2);
    cudaGetSymbolAddress((void**)&wt3,    g_wt3);

    const int SM64  = 4 * 128 * (64 + 8) * 2;    // 73728
    const int SM128 = 4 * 128 * (128 + 8) * 2;   // 139264
    cudaFuncSetAttribute((const void*)k_mma<64, 4>,  cudaFuncAttributeMaxDynamicSharedMemorySize, SM64);
    cudaFuncSetAttribute((const void*)k_mma<128, 4>, cudaFuncAttributeMaxDynamicSharedMemorySize, SM128);
    cudaFuncSetAttribute((const void*)k_mma3,        cudaFuncAttributeMaxDynamicSharedMemorySize, SM128);

    const int GN = (NN + 255) / 256;
    const int GE = (EE + 255) / 256;
    const int GW = (NN + 7) / 8;
    const int GT = (NN + 127) / 128;
    const int GP = (NN * HID + 255) / 256;
    const int NB = (NN + 1023) / 1024;   // 49

    // --- graph setup ---
    k_zero<<<GN, 256>>>();
    k_hist<<<GE, 256>>>(col, ea);
    k_dinv<<<GN, 256>>>();
    k_scan1<<<NB, 1024>>>();
    k_scan2<<<1, 64>>>(NB);
    k_scan3<<<GN, 256>>>();
    k_scatter<<<GE, 256>>>(row, col, ea);

    // --- weight prep (bf16 hi/lo, transposed) ---
    k_wprep1<<<(4 * 128 * 64 + 255) / 256, 256>>>(c1_w);
    k_wprep2<<<(4 * 128 * 128 + 255) / 256, 256>>>(c2_w);
    k_wprep3<<<(2 * 128 * 128 + 255) / 256, 256>>>(c3_w);

    // --- iteration-invariant pos hops + posacc ---
    k_prop3<<<GN, 256>>>(pp1, pos);
    k_prop3<<<GN, 256>>>(pp2, pp1);
    k_prop3<<<GN, 256>>>(pp3, pp2);
    k_posacc<<<GP, 256>>>(pos, c1_w);

    // --- up MLP -> z0 ---
    k_up<<<(NN + 3) / 4, 256>>>(x, up_w1, up_b1, up_w2, up_b2);

    // --- 21 gnn applications ---
    for (int it = 0; it < 21; it++) {
        // tag1: hops on z (64ch), tensor GEMM (+posacc, relu) -> h
        k_prop64<<<GW, 256>>>(p1, z);
        k_prop64<<<GW, 256>>>(p2, p1);
        k_prop64<<<GW, 256>>>(p3, p2);
        k_mma<64, 4><<<GT, 256, SM64>>>(z, p1, p2, p3, wt1, posacc, c1_b, h);

        // tag2: hops on h (128ch), tensor GEMM (relu) -> h
        k_prop128<<<GW, 256>>>(p1, h);
        k_prop128<<<GW, 256>>>(p2, p1);
        k_prop128<<<GW, 256>>>(p3, p2);
        k_mma<128, 4><<<GT, 256, SM128>>>(h, p1, p2, p3, wt2, nullptr, c2_b, h);

        // tag3: one merged GEMM launch (both W pairs), then 64ch prop chain
        k_mma3<<<GT, 256, SM128>>>(h, wt3, y0, y1, y2, y3);
        k_propadd64<<<GW, 256>>>(p1, y3, y2);
        k_propadd64<<<GW, 256>>>(p2, p1, y1);
        k_proplogsm<<<GW, 256>>>(p2, y0, c3_b);
    }

    // --- down MLP + write (out, z_star) ---
    k_down<<<GW, 256>>>((float*)d_out, dw1, db1, dw2, db2);

    (void)in_sizes; (void)n_in; (void)out_size;
}

// round 11
// speedup vs baseline: 1.2138x; 1.0520x over previous
#include <cuda_runtime.h>
#include <cuda_bf16.h>
#include <math.h>
#include <stdint.h>

#define NN 50000
#define EE 800000
#define EMB 64
#define HID 128

// ---------------- scratch (device globals; no allocation allowed) ----------------
__device__ float g_deg[NN];
__device__ float g_dinv[NN];
__device__ int   g_cnt[NN];
__device__ int   g_off[NN + 1];
__device__ int   g_cur[NN];
__device__ int   g_bsum[64];
__device__ int   g_srcs[EE];
__device__ float g_wsrt[EE];

__device__ __align__(16) float g_z[NN * EMB];
__device__ __align__(16) float g_h[NN * HID];
__device__ __align__(16) float g_p1[NN * HID];
__device__ __align__(16) float g_p2[NN * HID];
__device__ __align__(16) float g_p3[NN * HID];
__device__ __align__(16) float g_y0[NN * EMB];
__device__ __align__(16) float g_y1[NN * EMB];
__device__ __align__(16) float g_y2[NN * EMB];
__device__ __align__(16) float g_y3[NN * EMB];
__device__ __align__(16) float g_pp1[NN * 3];
__device__ __align__(16) float g_pp2[NN * 3];
__device__ __align__(16) float g_pp3[NN * 3];
__device__ __align__(16) float g_posacc[NN * HID];

// pre-split, pre-transposed weights: [hop][s=hi/lo][n(128)][k(CINH)] bf16
__device__ __align__(16) __nv_bfloat16 g_wt1[4 * 2 * 128 * 64];
__device__ __align__(16) __nv_bfloat16 g_wt2[4 * 2 * 128 * 128];
__device__ __align__(16) __nv_bfloat16 g_wt3[2 * 2 * 128 * 128];

__device__ __forceinline__ float gelu_exact(float x) {
    return 0.5f * x * (1.0f + erff(x * 0.70710678118654752f));
}

// fast fp32 pair -> packed bf16 hi/lo
__device__ __forceinline__ void split2f(float x, float y, uint32_t& hi, uint32_t& lo) {
    asm("cvt.rn.bf16x2.f32 %0, %1, %2;" : "=r"(hi) : "f"(y), "f"(x));
    float h0 = __uint_as_float(hi << 16);
    float h1 = __uint_as_float(hi & 0xFFFF0000u);
    float r0 = x - h0, r1 = y - h1;
    asm("cvt.rn.bf16x2.f32 %0, %1, %2;" : "=r"(lo) : "f"(r1), "f"(r0));
}

// ---------------- mma.sync helper (bf16, m16n8k16, fp32 acc) ----------------
__device__ __forceinline__ void mma16816(float* d, const uint32_t* a, uint32_t b0, uint32_t b1) {
    asm volatile(
        "mma.sync.aligned.m16n8k16.row.col.f32.bf16.bf16.f32 "
        "{%0,%1,%2,%3}, {%4,%5,%6,%7}, {%8,%9}, {%0,%1,%2,%3};"
        : "+f"(d[0]), "+f"(d[1]), "+f"(d[2]), "+f"(d[3])
        : "r"(a[0]), "r"(a[1]), "r"(a[2]), "r"(a[3]), "r"(b0), "r"(b1));
}

// ---------------- setup kernels ----------------
__global__ void k_zero() {
    int i = blockIdx.x * blockDim.x + threadIdx.x;
    if (i < NN) { g_deg[i] = 0.f; g_cnt[i] = 0; }
}

__global__ void k_hist(const int* __restrict__ col, const float* __restrict__ ea) {
    int e = blockIdx.x * blockDim.x + threadIdx.x;
    if (e < EE) {
        int c = col[e];
        atomicAdd(&g_deg[c], ea[e]);
        atomicAdd(&g_cnt[c], 1);
    }
}

__global__ void k_dinv() {
    int i = blockIdx.x * blockDim.x + threadIdx.x;
    if (i < NN) {
        float d = g_deg[i];
        g_dinv[i] = (d > 0.f) ? rsqrtf(d) : 0.f;
    }
}

__global__ void k_scan1() {
    __shared__ int sh[1024];
    int blk = blockIdx.x, tid = threadIdx.x;
    int i = blk * 1024 + tid;
    int v = (i < NN) ? g_cnt[i] : 0;
    sh[tid] = v;
    __syncthreads();
    for (int ofs = 1; ofs < 1024; ofs <<= 1) {
        int t = (tid >= ofs) ? sh[tid - ofs] : 0;
        __syncthreads();
        sh[tid] += t;
        __syncthreads();
    }
    if (i < NN) g_off[i] = sh[tid] - v;
    if (tid == 1023) g_bsum[blk] = sh[1023];
}

__global__ void k_scan2(int nblk) {
    __shared__ int sh[64];
    int tid = threadIdx.x;
    int v = (tid < nblk) ? g_bsum[tid] : 0;
    sh[tid] = v;
    __syncthreads();
    for (int ofs = 1; ofs < 64; ofs <<= 1) {
        int t = (tid >= ofs) ? sh[tid - ofs] : 0;
        __syncthreads();
        sh[tid] += t;
        __syncthreads();
    }
    g_bsum[tid] = sh[tid] - v;
}

__global__ void k_scan3() {
    int i = blockIdx.x * blockDim.x + threadIdx.x;
    if (i < NN) {
        int o = g_off[i] + g_bsum[i >> 10];
        g_off[i] = o;
        g_cur[i] = o;
    }
    if (i == 0) g_off[NN] = EE;
}

__global__ void k_scatter(const int* __restrict__ row, const int* __restrict__ col,
                          const float* __restrict__ ea) {
    int e = blockIdx.x * blockDim.x + threadIdx.x;
    if (e < EE) {
        int r = row[e], c = col[e];
        int p = atomicAdd(&g_cur[c], 1);
        g_srcs[p] = r;
        g_wsrt[p] = g_dinv[r] * ea[e] * g_dinv[c];
    }
}

// ---------------- weight prep ----------------
__device__ __forceinline__ void split_store(__nv_bfloat16* hi, __nv_bfloat16* lo, float w) {
    __nv_bfloat16 hb = __float2bfloat16(w);
    *hi = hb;
    *lo = __float2bfloat16(w - __bfloat162float(hb));
}

__global__ void k_wprep1(const float* __restrict__ c1w) {
    int idx = blockIdx.x * blockDim.x + threadIdx.x;
    if (idx >= 4 * 128 * 64) return;
    int hop = idx / (128 * 64);
    int r = idx - hop * 128 * 64;
    int n = r >> 6, k = r & 63;
    float w = c1w[hop * 67 * 128 + k * 128 + n];
    size_t b = ((size_t)(hop * 2) * 128 + n) * 64 + k;
    split_store(&g_wt1[b], &g_wt1[b + 128 * 64], w);
}

__global__ void k_wprep2(const float* __restrict__ c2w) {
    int idx = blockIdx.x * blockDim.x + threadIdx.x;
    if (idx >= 4 * 128 * 128) return;
    int hop = idx / (128 * 128);
    int r = idx - hop * 128 * 128;
    int n = r >> 7, k = r & 127;
    float w = c2w[hop * 128 * 128 + k * 128 + n];
    size_t b = ((size_t)(hop * 2) * 128 + n) * 128 + k;
    split_store(&g_wt2[b], &g_wt2[b + 128 * 128], w);
}

__global__ void k_wprep3(const float* __restrict__ c3w) {
    int idx = blockIdx.x * blockDim.x + threadIdx.x;
    if (idx >= 2 * 128 * 128) return;
    int pair = idx / (128 * 128);
    int r = idx - pair * 128 * 128;
    int n = r >> 7, k = r & 127;
    int wk = pair * 2 + (n >> 6);
    int nn = n & 63;
    float w = c3w[wk * 128 * 64 + k * 64 + nn];
    size_t b = ((size_t)(pair * 2) * 128 + n) * 128 + k;
    split_store(&g_wt3[b], &g_wt3[b + 128 * 128], w);
}

// ---------------- pos hops + posacc ----------------
__global__ void k_prop3(float* __restrict__ dst, const float* __restrict__ src) {
    int j = blockIdx.x * blockDim.x + threadIdx.x;
    if (j >= NN) return;
    int beg = g_off[j], end = g_off[j + 1];
    float a0 = 0.f, a1 = 0.f, a2 = 0.f;
    for (int e = beg; e < end; e++) {
        int s = g_srcs[e];
        float w = g_wsrt[e];
        a0 += w * src[s * 3 + 0];
        a1 += w * src[s * 3 + 1];
        a2 += w * src[s * 3 + 2];
    }
    dst[j * 3 + 0] = a0; dst[j * 3 + 1] = a1; dst[j * 3 + 2] = a2;
}

__global__ void k_posacc(const float* __restrict__ pos, const float* __restrict__ c1w) {
    int idx = blockIdx.x * blockDim.x + threadIdx.x;
    if (idx >= NN * HID) return;
    int n = idx >> 7, c = idx & 127;
    const float* pps[4] = {pos, g_pp1, g_pp2, g_pp3};
    float acc = 0.f;
#pragma unroll
    for (int k = 0; k < 4; k++) {
        const float* pp = pps[k] + n * 3;
        const float* wr = c1w + k * 67 * 128 + 64 * 128 + c;
        acc += pp[0] * wr[0] + pp[1] * wr[128] + pp[2] * wr[256];
    }
    g_posacc[idx] = acc;
}

// ---------------- up MLP ----------------
__global__ __launch_bounds__(256) void k_up(const float* __restrict__ x,
                                            const float* __restrict__ w1, const float* __restrict__ b1,
                                            const float* __restrict__ w2, const float* __restrict__ b2) {
    __shared__ float sw2[64 * 64];
    __shared__ float hid[4][64];
    int tid = threadIdx.x;
#pragma unroll
    for (int i = 0; i < 16; i++) sw2[tid * 16 + i] = w2[tid * 16 + i];
    int local = tid >> 6;
    int c = tid & 63;
    int node = blockIdx.x * 4 + local;
    float h = 0.f;
    if (node < NN) {
        h = b1[c];
#pragma unroll
        for (int i = 0; i < 4; i++) h += x[node * 4 + i] * w1[i * 64 + c];
        h = gelu_exact(h);
    }
    hid[local][c] = h;
    __syncthreads();
    if (node < NN) {
        float o = b2[c];
#pragma unroll
        for (int j = 0; j < 64; j++) o += hid[local][j] * sw2[j * 64 + c];
        g_z[node * 64 + c] = o;
    }
}

// ---------------- propagation kernels (CSR, warp per node, 4-way unroll) ----------
__global__ __launch_bounds__(256) void k_prop64(float* __restrict__ dst, const float* __restrict__ src) {
    int wrp = threadIdx.x >> 5, lane = threadIdx.x & 31;
    int j = blockIdx.x * 8 + wrp;
    if (j >= NN) return;
    int beg = g_off[j], end = g_off[j + 1];
    float2 a0 = {0.f,0.f}, a1 = {0.f,0.f}, a2 = {0.f,0.f}, a3 = {0.f,0.f};
    int e = beg;
    for (; e + 4 <= end; e += 4) {
        int s0 = g_srcs[e], s1 = g_srcs[e+1], s2 = g_srcs[e+2], s3 = g_srcs[e+3];
        float w0 = g_wsrt[e], w1 = g_wsrt[e+1], w2 = g_wsrt[e+2], w3 = g_wsrt[e+3];
        float2 v0 = *(const float2*)(src + (size_t)s0 * 64 + lane * 2);
        float2 v1 = *(const float2*)(src + (size_t)s1 * 64 + lane * 2);
        float2 v2 = *(const float2*)(src + (size_t)s2 * 64 + lane * 2);
        float2 v3 = *(const float2*)(src + (size_t)s3 * 64 + lane * 2);
        a0.x = fmaf(w0, v0.x, a0.x); a0.y = fmaf(w0, v0.y, a0.y);
        a1.x = fmaf(w1, v1.x, a1.x); a1.y = fmaf(w1, v1.y, a1.y);
        a2.x = fmaf(w2, v2.x, a2.x); a2.y = fmaf(w2, v2.y, a2.y);
        a3.x = fmaf(w3, v3.x, a3.x); a3.y = fmaf(w3, v3.y, a3.y);
    }
    for (; e < end; e++) {
        int s0 = g_srcs[e];
        float w0 = g_wsrt[e];
        float2 v0 = *(const float2*)(src + (size_t)s0 * 64 + lane * 2);
        a0.x = fmaf(w0, v0.x, a0.x); a0.y = fmaf(w0, v0.y, a0.y);
    }
    float2 r;
    r.x = (a0.x + a1.x) + (a2.x + a3.x);
    r.y = (a0.y + a1.y) + (a2.y + a3.y);
    *(float2*)(dst + (size_t)j * 64 + lane * 2) = r;
}

__global__ __launch_bounds__(256) void k_prop128(float* __restrict__ dst, const float* __restrict__ src) {
    int wrp = threadIdx.x >> 5, lane = threadIdx.x & 31;
    int j = blockIdx.x * 8 + wrp;
    if (j >= NN) return;
    int beg = g_off[j], end = g_off[j + 1];
    float4 a0 = {0.f,0.f,0.f,0.f}, a1 = {0.f,0.f,0.f,0.f};
    float4 a2 = {0.f,0.f,0.f,0.f}, a3 = {0.f,0.f,0.f,0.f};
    int e = beg;
    for (; e + 4 <= end; e += 4) {
        int s0 = g_srcs[e], s1 = g_srcs[e+1], s2 = g_srcs[e+2], s3 = g_srcs[e+3];
        float w0 = g_wsrt[e], w1 = g_wsrt[e+1], w2 = g_wsrt[e+2], w3 = g_wsrt[e+3];
        float4 v0 = *(const float4*)(src + (size_t)s0 * 128 + lane * 4);
        float4 v1 = *(const float4*)(src + (size_t)s1 * 128 + lane * 4);
        float4 v2 = *(const float4*)(src + (size_t)s2 * 128 + lane * 4);
        float4 v3 = *(const float4*)(src + (size_t)s3 * 128 + lane * 4);
        a0.x = fmaf(w0, v0.x, a0.x); a0.y = fmaf(w0, v0.y, a0.y);
        a0.z = fmaf(w0, v0.z, a0.z); a0.w = fmaf(w0, v0.w, a0.w);
        a1.x = fmaf(w1, v1.x, a1.x); a1.y = fmaf(w1, v1.y, a1.y);
        a1.z = fmaf(w1, v1.z, a1.z); a1.w = fmaf(w1, v1.w, a1.w);
        a2.x = fmaf(w2, v2.x, a2.x); a2.y = fmaf(w2, v2.y, a2.y);
        a2.z = fmaf(w2, v2.z, a2.z); a2.w = fmaf(w2, v2.w, a2.w);
        a3.x = fmaf(w3, v3.x, a3.x); a3.y = fmaf(w3, v3.y, a3.y);
        a3.z = fmaf(w3, v3.z, a3.z); a3.w = fmaf(w3, v3.w, a3.w);
    }
    for (; e < end; e++) {
        int s0 = g_srcs[e];
        float w0 = g_wsrt[e];
        float4 v0 = *(const float4*)(src + (size_t)s0 * 128 + lane * 4);
        a0.x = fmaf(w0, v0.x, a0.x); a0.y = fmaf(w0, v0.y, a0.y);
        a0.z = fmaf(w0, v0.z, a0.z); a0.w = fmaf(w0, v0.w, a0.w);
    }
    float4 r;
    r.x = (a0.x + a1.x) + (a2.x + a3.x);
    r.y = (a0.y + a1.y) + (a2.y + a3.y);
    r.z = (a0.z + a1.z) + (a2.z + a3.z);
    r.w = (a0.w + a1.w) + (a2.w + a3.w);
    *(float4*)(dst + (size_t)j * 128 + lane * 4) = r;
}

__global__ __launch_bounds__(256) void k_propadd64(float* __restrict__ dst, const float* __restrict__ src,
                                                   const float* __restrict__ add) {
    int wrp = threadIdx.x >> 5, lane = threadIdx.x & 31;
    int j = blockIdx.x * 8 + wrp;
    if (j >= NN) return;
    int beg = g_off[j], end = g_off[j + 1];
    float2 a0 = {0.f,0.f}, a1 = {0.f,0.f}, a2 = {0.f,0.f}, a3 = {0.f,0.f};
    int e = beg;
    for (; e + 4 <= end; e += 4) {
        int s0 = g_srcs[e], s1 = g_srcs[e+1], s2 = g_srcs[e+2], s3 = g_srcs[e+3];
        float w0 = g_wsrt[e], w1 = g_wsrt[e+1], w2 = g_wsrt[e+2], w3 = g_wsrt[e+3];
        float2 v0 = *(const float2*)(src + (size_t)s0 * 64 + lane * 2);
        float2 v1 = *(const float2*)(src + (size_t)s1 * 64 + lane * 2);
        float2 v2 = *(const float2*)(src + (size_t)s2 * 64 + lane * 2);
        float2 v3 = *(const float2*)(src + (size_t)s3 * 64 + lane * 2);
        a0.x = fmaf(w0, v0.x, a0.x); a0.y = fmaf(w0, v0.y, a0.y);
        a1.x = fmaf(w1, v1.x, a1.x); a1.y = fmaf(w1, v1.y, a1.y);
        a2.x = fmaf(w2, v2.x, a2.x); a2.y = fmaf(w2, v2.y, a2.y);
        a3.x = fmaf(w3, v3.x, a3.x); a3.y = fmaf(w3, v3.y, a3.y);
    }
    for (; e < end; e++) {
        int s0 = g_srcs[e];
        float w0 = g_wsrt[e];
        float2 v0 = *(const float2*)(src + (size_t)s0 * 64 + lane * 2);
        a0.x = fmaf(w0, v0.x, a0.x); a0.y = fmaf(w0, v0.y, a0.y);
    }
    float2 ad = *(const float2*)(add + (size_t)j * 64 + lane * 2);
    float2 r;
    r.x = (a0.x + a1.x) + (a2.x + a3.x) + ad.x;
    r.y = (a0.y + a1.y) + (a2.y + a3.y) + ad.y;
    *(float2*)(dst + (size_t)j * 64 + lane * 2) = r;
}

__global__ __launch_bounds__(256) void k_proplogsm(const float* __restrict__ src,
                                                   const float* __restrict__ add,
                                                   const float* __restrict__ bias) {
    int wrp = threadIdx.x >> 5, lane = threadIdx.x & 31;
    int j = blockIdx.x * 8 + wrp;
    if (j >= NN) return;
    int beg = g_off[j], end = g_off[j + 1];
    float2 a0 = {0.f,0.f}, a1 = {0.f,0.f}, a2 = {0.f,0.f}, a3 = {0.f,0.f};
    int e = beg;
    for (; e + 4 <= end; e += 4) {
        int s0 = g_srcs[e], s1 = g_srcs[e+1], s2 = g_srcs[e+2], s3 = g_srcs[e+3];
        float w0 = g_wsrt[e], w1 = g_wsrt[e+1], w2 = g_wsrt[e+2], w3 = g_wsrt[e+3];
        float2 v0 = *(const float2*)(src + (size_t)s0 * 64 + lane * 2);
        float2 v1 = *(const float2*)(src + (size_t)s1 * 64 + lane * 2);
        float2 v2 = *(const float2*)(src + (size_t)s2 * 64 + lane * 2);
        float2 v3 = *(const float2*)(src + (size_t)s3 * 64 + lane * 2);
        a0.x = fmaf(w0, v0.x, a0.x); a0.y = fmaf(w0, v0.y, a0.y);
        a1.x = fmaf(w1, v1.x, a1.x); a1.y = fmaf(w1, v1.y, a1.y);
        a2.x = fmaf(w2, v2.x, a2.x); a2.y = fmaf(w2, v2.y, a2.y);
        a3.x = fmaf(w3, v3.x, a3.x); a3.y = fmaf(w3, v3.y, a3.y);
    }
    for (; e < end; e++) {
        int s0 = g_srcs[e];
        float w0 = g_wsrt[e];
        float2 v0 = *(const float2*)(src + (size_t)s0 * 64 + lane * 2);
        a0.x = fmaf(w0, v0.x, a0.x); a0.y = fmaf(w0, v0.y, a0.y);
    }
    float2 ad = *(const float2*)(add + (size_t)j * 64 + lane * 2);
    float v0 = (a0.x + a1.x) + (a2.x + a3.x) + ad.x + bias[2 * lane];
    float v1 = (a0.y + a1.y) + (a2.y + a3.y) + ad.y + bias[2 * lane + 1];
    float m = fmaxf(v0, v1);
#pragma unroll
    for (int o = 16; o; o >>= 1) m = fmaxf(m, __shfl_xor_sync(0xffffffffu, m, o));
    float s = expf(v0 - m) + expf(v1 - m);
#pragma unroll
    for (int o = 16; o; o >>= 1) s += __shfl_xor_sync(0xffffffffu, s, o);
    float l = m + logf(s);
    g_z[j * 64 + 2 * lane]     = v0 - l;
    g_z[j * 64 + 2 * lane + 1] = v1 - l;
}

// ---------------- tensor GEMM via mma.sync (M=64 CTA tiles, 2M x 4N warps) --------
// D[64 rows, 128 cols] = sum_{hop} A_hop[rows, CINH] @ Wt_hop^T
// out0[row*128+c] = relu(D + addend? + bias)
template <int CINH, int NHOPS>
__global__ __launch_bounds__(256)
void k_mma(const float* __restrict__ A0, const float* __restrict__ A1,
           const float* __restrict__ A2, const float* __restrict__ A3,
           const __nv_bfloat16* __restrict__ Wt,
           const float* __restrict__ addend, const float* __restrict__ bias,
           float* __restrict__ out0) {
    constexpr int ASTR = CINH + 8;
    extern __shared__ __align__(16) char sm[];
    __nv_bfloat16* sAhi = (__nv_bfloat16*)sm;
    __nv_bfloat16* sAlo = sAhi + 64 * ASTR;
    __nv_bfloat16* sWhi = sAlo + 64 * ASTR;
    __nv_bfloat16* sWlo = sWhi + 128 * ASTR;

    int tid = threadIdx.x, wid = tid >> 5, lane = tid & 31;
    int wm = wid & 1, wn = wid >> 1;      // 2 m-tiles x 4 n-tiles
    int grp = lane >> 2, tig = lane & 3;

    float acc[2][4][4];
#pragma unroll
    for (int i = 0; i < 2; i++)
#pragma unroll
        for (int j = 0; j < 4; j++)
#pragma unroll
            for (int q = 0; q < 4; q++) acc[i][j][q] = 0.f;

    const float* As[4] = {A0, A1, A2, A3};
    int row0 = blockIdx.x * 64;
    constexpr int KQ4 = CINH / 4;
    constexpr int KQ8 = CINH / 8;

    for (int h = 0; h < NHOPS; h++) {
        if (h) __syncthreads();
        const float* Ah = As[h];
        for (int u = tid; u < 64 * KQ4; u += 256) {
            int r = u / KQ4;
            int k4 = (u - r * KQ4) * 4;
            int grow = row0 + r;
            float4 f;
            if (grow < NN) f = *(const float4*)(Ah + (size_t)grow * CINH + k4);
            else { f.x = f.y = f.z = f.w = 0.f; }
            uint32_t hp0, lp0, hp1, lp1;
            split2f(f.x, f.y, hp0, lp0);
            split2f(f.z, f.w, hp1, lp1);
            *(uint2*)(sAhi + r * ASTR + k4) = make_uint2(hp0, hp1);
            *(uint2*)(sAlo + r * ASTR + k4) = make_uint2(lp0, lp1);
        }
        for (int u = tid; u < 2 * 128 * KQ8; u += 256) {
            int s = u / (128 * KQ8);
            int rem = u - s * 128 * KQ8;
            int n = rem / KQ8;
            int k8 = (rem - n * KQ8) * 8;
            uint4 vv = *(const uint4*)(Wt + ((size_t)((h * 2 + s) * 128 + n)) * CINH + k8);
            *(uint4*)((s ? sWlo : sWhi) + n * ASTR + k8) = vv;
        }
        __syncthreads();

#pragma unroll
        for (int pass = 0; pass < 3; pass++) {
            const __nv_bfloat16* Ab = (pass == 2) ? sAlo : sAhi;
            const __nv_bfloat16* Wb = (pass == 1) ? sWlo : sWhi;
#pragma unroll
            for (int k8 = 0; k8 < CINH / 16; k8++) {
                uint32_t a[2][4];
                const __nv_bfloat16* ab = Ab + (wm * 32 + grp) * ASTR + k8 * 16 + 2 * tig;
#pragma unroll
                for (int ms = 0; ms < 2; ms++) {
                    const __nv_bfloat16* p = ab + ms * 16 * ASTR;
                    a[ms][0] = *(const uint32_t*)p;
                    a[ms][1] = *(const uint32_t*)(p + 8 * ASTR);
                    a[ms][2] = *(const uint32_t*)(p + 8);
                    a[ms][3] = *(const uint32_t*)(p + 8 * ASTR + 8);
                }
                const __nv_bfloat16* bb = Wb + (wn * 32 + grp) * ASTR + k8 * 16 + 2 * tig;
#pragma unroll
                for (int n8 = 0; n8 < 4; n8++) {
                    uint32_t b0 = *(const uint32_t*)(bb + n8 * 8 * ASTR);
                    uint32_t b1 = *(const uint32_t*)(bb + n8 * 8 * ASTR + 8);
                    mma16816(acc[0][n8], a[0], b0, b1);
                    mma16816(acc[1][n8], a[1], b0, b1);
                }
            }
        }
    }

#pragma unroll
    for (int ms = 0; ms < 2; ms++) {
        int r0 = row0 + wm * 32 + ms * 16 + grp;
        int r1 = r0 + 8;
#pragma unroll
        for (int n8 = 0; n8 < 4; n8++) {
            int cb = wn * 32 + n8 * 8 + 2 * tig;
            float* d = acc[ms][n8];
            float b0v = __ldg(bias + cb), b1v = __ldg(bias + cb + 1);
            if (r0 < NN) {
                float v0 = d[0] + b0v, v1 = d[1] + b1v;
                if (addend) {
                    float2 ad = *(const float2*)(addend + (size_t)r0 * 128 + cb);
                    v0 += ad.x; v1 += ad.y;
                }
                float2 o; o.x = fmaxf(v0, 0.f); o.y = fmaxf(v1, 0.f);
                *(float2*)(out0 + (size_t)r0 * 128 + cb) = o;
            }
            if (r1 < NN) {
                float v0 = d[2] + b0v, v1 = d[3] + b1v;
                if (addend) {
                    float2 ad = *(const float2*)(addend + (size_t)r1 * 128 + cb);
                    v0 += ad.x; v1 += ad.y;
                }
                float2 o; o.x = fmaxf(v0, 0.f); o.y = fmaxf(v1, 0.f);
                *(float2*)(out0 + (size_t)r1 * 128 + cb) = o;
            }
        }
    }
}

// ---------------- tag3 GEMM: M=64 tiles, one A fill, two W pair sets -> y0..y3 -----
__global__ __launch_bounds__(256)
void k_mma3(const float* __restrict__ A, const __nv_bfloat16* __restrict__ Wt,
            float* __restrict__ y0, float* __restrict__ y1,
            float* __restrict__ y2, float* __restrict__ y3) {
    constexpr int CINH = 128;
    constexpr int ASTR = CINH + 8;
    extern __shared__ __align__(16) char sm[];
    __nv_bfloat16* sAhi = (__nv_bfloat16*)sm;
    __nv_bfloat16* sAlo = sAhi + 64 * ASTR;
    __nv_bfloat16* sWhi = sAlo + 64 * ASTR;
    __nv_bfloat16* sWlo = sWhi + 128 * ASTR;

    int tid = threadIdx.x, wid = tid >> 5, lane = tid & 31;
    int wm = wid & 1, wn = wid >> 1;
    int grp = lane >> 2, tig = lane & 3;
    int row0 = blockIdx.x * 64;
    constexpr int KQ4 = CINH / 4;
    constexpr int KQ8 = CINH / 8;

    for (int u = tid; u < 64 * KQ4; u += 256) {
        int r = u / KQ4;
        int k4 = (u - r * KQ4) * 4;
        int grow = row0 + r;
        float4 f;
        if (grow < NN) f = *(const float4*)(A + (size_t)grow * CINH + k4);
        else { f.x = f.y = f.z = f.w = 0.f; }
        uint32_t hp0, lp0, hp1, lp1;
        split2f(f.x, f.y, hp0, lp0);
        split2f(f.z, f.w, hp1, lp1);
        *(uint2*)(sAhi + r * ASTR + k4) = make_uint2(hp0, hp1);
        *(uint2*)(sAlo + r * ASTR + k4) = make_uint2(lp0, lp1);
    }

    for (int set = 0; set < 2; set++) {
        const __nv_bfloat16* Wp = Wt + (size_t)set * 2 * 128 * CINH;
        for (int u = tid; u < 2 * 128 * KQ8; u += 256) {
            int s = u / (128 * KQ8);
            int rem = u - s * 128 * KQ8;
            int n = rem / KQ8;
            int k8 = (rem - n * KQ8) * 8;
            uint4 vv = *(const uint4*)(Wp + ((size_t)(s * 128 + n)) * CINH + k8);
            *(uint4*)((s ? sWlo : sWhi) + n * ASTR + k8) = vv;
        }
        __syncthreads();

        float acc[2][4][4];
#pragma unroll
        for (int i = 0; i < 2; i++)
#pragma unroll
            for (int j = 0; j < 4; j++)
#pragma unroll
                for (int q = 0; q < 4; q++) acc[i][j][q] = 0.f;

#pragma unroll
        for (int pass = 0; pass < 3; pass++) {
            const __nv_bfloat16* Ab = (pass == 2) ? sAlo : sAhi;
            const __nv_bfloat16* Wb = (pass == 1) ? sWlo : sWhi;
#pragma unroll
            for (int k8 = 0; k8 < CINH / 16; k8++) {
                uint32_t a[2][4];
                const __nv_bfloat16* ab = Ab + (wm * 32 + grp) * ASTR + k8 * 16 + 2 * tig;
#pragma unroll
                for (int ms = 0; ms < 2; ms++) {
                    const __nv_bfloat16* p = ab + ms * 16 * ASTR;
                    a[ms][0] = *(const uint32_t*)p;
                    a[ms][1] = *(const uint32_t*)(p + 8 * ASTR);
                    a[ms][2] = *(const uint32_t*)(p + 8);
                    a[ms][3] = *(const uint32_t*)(p + 8 * ASTR + 8);
                }
                const __nv_bfloat16* bb = Wb + (wn * 32 + grp) * ASTR + k8 * 16 + 2 * tig;
#pragma unroll
                for (int n8 = 0; n8 < 4; n8++) {
                    uint32_t b0 = *(const uint32_t*)(bb + n8 * 8 * ASTR);
                    uint32_t b1 = *(const uint32_t*)(bb + n8 * 8 * ASTR + 8);
                    mma16816(acc[0][n8], a[0], b0, b1);
                    mma16816(acc[1][n8], a[1], b0, b1);
                }
            }
        }

        // global col = wn*32 + n8*8 + 2*tig in [0,128): first 64 -> oA, else oB
        float* oA = set ? y2 : y0;
        float* oB = set ? y3 : y1;
        float* op = (wn < 2) ? oA : oB;
        int cbase = (wn & 1) * 32;
#pragma unroll
        for (int ms = 0; ms < 2; ms++) {
            int r0 = row0 + wm * 32 + ms * 16 + grp;
            int r1 = r0 + 8;
#pragma unroll
            for (int n8 = 0; n8 < 4; n8++) {
                int cc = cbase + n8 * 8 + 2 * tig;
                float* d = acc[ms][n8];
                if (r0 < NN) {
                    float2 o; o.x = d[0]; o.y = d[1];
                    *(float2*)(op + (size_t)r0 * 64 + cc) = o;
                }
                if (r1 < NN) {
                    float2 o; o.x = d[2]; o.y = d[3];
                    *(float2*)(op + (size_t)r1 * 64 + cc) = o;
                }
            }
        }
        __syncthreads();
    }
}

// ---------------- down MLP + output write ----------------
__global__ __launch_bounds__(256) void k_down(float* __restrict__ out,
                                              const float* __restrict__ w1, const float* __restrict__ b1,
                                              const float* __restrict__ w2, const float* __restrict__ b2) {
    int wrp = threadIdx.x >> 5, lane = threadIdx.x & 31;
    int j = blockIdx.x * 8 + wrp;
    if (j >= NN) return;
    float z0 = g_z[j * 64 + lane];
    float z1 = g_z[j * 64 + 32 + lane];
    out[NN + j * 64 + lane] = z0;
    out[NN + j * 64 + 32 + lane] = z1;
    float d = z0 * w1[lane] + z1 * w1[32 + lane];
#pragma unroll
    for (int o = 16; o; o >>= 1) d += __shfl_xor_sync(0xffffffffu, d, o);
    if (lane == 0) out[j] = gelu_exact(d + b1[0]) * w2[0] + b2[0];
}

// ---------------- host orchestration ----------------
extern "C" void kernel_launch(void* const* d_in, const int* in_sizes, int n_in,
                              void* d_out, int out_size) {
    const float* x      = (const float*)d_in[0];
    const float* pos    = (const float*)d_in[1];
    const float* ea     = (const float*)d_in[2];
    const float* up_w1  = (const float*)d_in[3];
    const float* up_b1  = (const float*)d_in[4];
    const float* up_w2  = (const float*)d_in[5];
    const float* up_b2  = (const float*)d_in[6];
    const float* c1_w   = (const float*)d_in[7];
    const float* c1_b   = (const float*)d_in[8];
    const float* c2_w   = (const float*)d_in[9];
    const float* c2_b   = (const float*)d_in[10];
    const float* c3_w   = (const float*)d_in[11];
    const float* c3_b   = (const float*)d_in[12];
    const float* dw1    = (const float*)d_in[13];
    const float* db1    = (const float*)d_in[14];
    const float* dw2    = (const float*)d_in[15];
    const float* db2    = (const float*)d_in[16];
    const int*   ei     = (const int*)d_in[17];
    const int* row = ei;
    const int* col = ei + EE;

    float *z, *h, *p1, *p2, *p3, *y0, *y1, *y2, *y3, *pp1, *pp2, *pp3, *posacc;
    __nv_bfloat16 *wt1, *wt2, *wt3;
    cudaGetSymbolAddress((void**)&z,      g_z);
    cudaGetSymbolAddress((void**)&h,      g_h);
    cudaGetSymbolAddress((void**)&p1,     g_p1);
    cudaGetSymbolAddress((void**)&p2,     g_p2);
    cudaGetSymbolAddress((void**)&p3,     g_p3);
    cudaGetSymbolAddress((void**)&y0,     g_y0);
    cudaGetSymbolAddress((void**)&y1,     g_y1);
    cudaGetSymbolAddress((void**)&y2,     g_y2);
    cudaGetSymbolAddress((void**)&y3,     g_y3);
    cudaGetSymbolAddress((void**)&pp1,    g_pp1);
    cudaGetSymbolAddress((void**)&pp2,    g_pp2);
    cudaGetSymbolAddress((void**)&pp3,    g_pp3);
    cudaGetSymbolAddress((void**)&posacc, g_posacc);
    cudaGetSymbolAddress((void**)&wt1,    g_wt1);
    cudaGetSymbolAddress((void**)&wt2,    g_wt2);
    cudaGetSymbolAddress((void**)&wt3,    g_wt3);

    const int SM64  = (2 * 64 + 2 * 128) * (64 + 8) * 2;    // 55296
    const int SM128 = (2 * 64 + 2 * 128) * (128 + 8) * 2;   // 104448
    cudaFuncSetAttribute((const void*)k_mma<64, 4>,  cudaFuncAttributeMaxDynamicSharedMemorySize, SM64);
    cudaFuncSetAttribute((const void*)k_mma<128, 4>, cudaFuncAttributeMaxDynamicSharedMemorySize, SM128);
    cudaFuncSetAttribute((const void*)k_mma3,        cudaFuncAttributeMaxDynamicSharedMemorySize, SM128);

    const int GN = (NN + 255) / 256;
    const int GE = (EE + 255) / 256;
    const int GW = (NN + 7) / 8;
    const int GT = (NN + 63) / 64;       // M=64 tiles -> 782 CTAs
    const int GP = (NN * HID + 255) / 256;
    const int NB = (NN + 1023) / 1024;

    // --- graph setup ---
    k_zero<<<GN, 256>>>();
    k_hist<<<GE, 256>>>(col, ea);
    k_dinv<<<GN, 256>>>();
    k_scan1<<<NB, 1024>>>();
    k_scan2<<<1, 64>>>(NB);
    k_scan3<<<GN, 256>>>();
    k_scatter<<<GE, 256>>>(row, col, ea);

    // --- weight prep ---
    k_wprep1<<<(4 * 128 * 64 + 255) / 256, 256>>>(c1_w);
    k_wprep2<<<(4 * 128 * 128 + 255) / 256, 256>>>(c2_w);
    k_wprep3<<<(2 * 128 * 128 + 255) / 256, 256>>>(c3_w);

    // --- iteration-invariant pos hops + posacc ---
    k_prop3<<<GN, 256>>>(pp1, pos);
    k_prop3<<<GN, 256>>>(pp2, pp1);
    k_prop3<<<GN, 256>>>(pp3, pp2);
    k_posacc<<<GP, 256>>>(pos, c1_w);

    // --- up MLP -> z0 ---
    k_up<<<(NN + 3) / 4, 256>>>(x, up_w1, up_b1, up_w2, up_b2);

    // --- 21 gnn applications ---
    for (int it = 0; it < 21; it++) {
        k_prop64<<<GW, 256>>>(p1, z);
        k_prop64<<<GW, 256>>>(p2, p1);
        k_prop64<<<GW, 256>>>(p3, p2);
        k_mma<64, 4><<<GT, 256, SM64>>>(z, p1, p2, p3, wt1, posacc, c1_b, h);

        k_prop128<<<GW, 256>>>(p1, h);
        k_prop128<<<GW, 256>>>(p2, p1);
        k_prop128<<<GW, 256>>>(p3, p2);
        k_mma<128, 4><<<GT, 256, SM128>>>(h, p1, p2, p3, wt2, nullptr, c2_b, h);

        k_mma3<<<GT, 256, SM128>>>(h, wt3, y0, y1, y2, y3);
        k_propadd64<<<GW, 256>>>(p1, y3, y2);
        k_propadd64<<<GW, 256>>>(p2, p1, y1);
        k_proplogsm<<<GW, 256>>>(p2, y0, c3_b);
    }

    // --- down MLP + write (out, z_star) ---
    k_down<<<GW, 256>>>((float*)d_out, dw1, db1, dw2, db2);

    (void)in_sizes; (void)n_in; (void)out_size;
}